// round 3
// baseline (speedup 1.0000x reference)
#include <cuda_runtime.h>

// ---------------------------------------------------------------------------
// E=2,000,000 edges, N_S=N_T=100,000.
//   k0: zero segment-sum accumulators
//   k1: per-edge MLP (3->64->64->64->1, LeakyReLU+LayerNorm) -> y[e],
//       atomicAdd into sum_s[src], sum_t[dst]
//   k2: coef MLP (4->32->1, ReLU+LayerNorm) -> out[e] = y[e]*coef[e]
// No dynamic shared memory anywhere (R1 failure: 48KB dynamic + static
// exceeded the no-attribute launch limit and poisoned graph capture).
// ---------------------------------------------------------------------------

#define MAX_E  2000000
#define MAX_N  100000
#define EPSLN  1e-5f
#define SLOPE  0.01f

__device__ float g_y[MAX_E];
__device__ float g_sum_s[MAX_N];
__device__ float g_sum_t[MAX_N];

// ---------------------------------------------------------------------------
__global__ void zero_kernel(int ns, int nt) {
    int i = blockIdx.x * blockDim.x + threadIdx.x;
    if (i < ns) g_sum_s[i] = 0.0f;
    if (i < nt) g_sum_t[i] = 0.0f;
}

// ---------------------------------------------------------------------------
#define BLK 64

__device__ __forceinline__ void lnorm64(float h[64], const float* __restrict__ w,
                                        const float* __restrict__ b) {
    float s = 0.f;
#pragma unroll
    for (int k = 0; k < 64; k++) s += h[k];
    float m = s * (1.0f / 64.0f);
    float v = 0.f;
#pragma unroll
    for (int k = 0; k < 64; k++) { float d = h[k] - m; v += d * d; }
    v *= (1.0f / 64.0f);
    float inv = rsqrtf(v + EPSLN);
#pragma unroll
    for (int k = 0; k < 64; k++) h[k] = (h[k] - m) * inv * w[k] + b[k];
}

// dense 64x64 + leaky relu, fully unrolled, register double-buffer (no scratch)
__device__ __forceinline__ void layer64(float h[64], const float* __restrict__ W,
                                        const float* __restrict__ b) {
    float g[64];
#pragma unroll
    for (int j = 0; j < 64; j++) {
        float acc = b[j];
        const float4* row = (const float4*)(W + j * 64);
#pragma unroll
        for (int k = 0; k < 16; k++) {
            float4 a = row[k];
            acc += a.x * h[4 * k] + a.y * h[4 * k + 1] + a.z * h[4 * k + 2] + a.w * h[4 * k + 3];
        }
        g[j] = acc > 0.f ? acc : SLOPE * acc;
    }
#pragma unroll
    for (int k = 0; k < 64; k++) h[k] = g[k];
}

__global__ __launch_bounds__(BLK)
void edge_kernel(const float* __restrict__ x_s, const float* __restrict__ x_t,
                 const int* __restrict__ ei, const float* __restrict__ ea,
                 const float* __restrict__ w0, const float* __restrict__ b0,
                 const float* __restrict__ w1, const float* __restrict__ b1,
                 const float* __restrict__ w2, const float* __restrict__ b2,
                 const float* __restrict__ w3, const float* __restrict__ b3,
                 const float* __restrict__ lnw, const float* __restrict__ lnb,
                 int E) {
    __shared__ float w1s[4096];        // 16KB
    __shared__ float w2s[4096];        // 16KB
    __shared__ float w0s[192], b0s[64], b1s[64], b2s[64], w3s[64];
    __shared__ float lnws[192], lnbs[192];
    __shared__ float b3s;

    int tid = threadIdx.x;
    for (int i = tid; i < 4096; i += BLK) { w1s[i] = w1[i]; w2s[i] = w2[i]; }
    for (int i = tid; i < 192; i += BLK) { w0s[i] = w0[i]; lnws[i] = lnw[i]; lnbs[i] = lnb[i]; }
    if (tid < 64) { b0s[tid] = b0[tid]; b1s[tid] = b1[tid]; b2s[tid] = b2[tid]; w3s[tid] = w3[tid]; }
    if (tid == 0) b3s = b3[0];
    __syncthreads();

    int e = blockIdx.x * BLK + tid;
    bool active = (e < E);
    int eidx = active ? e : 0;
    int src = ei[eidx];
    int dst = ei[E + eidx];
    float xsd = x_s[src * 2 + 1];
    float xsc = x_t[dst * 2 + 1];
    float att = ea[eidx];

    float h[64];
#pragma unroll
    for (int j = 0; j < 64; j++) {
        float t = w0s[j * 3] * xsd + w0s[j * 3 + 1] * xsc + w0s[j * 3 + 2] * att + b0s[j];
        h[j] = t > 0.f ? t : SLOPE * t;
    }
    lnorm64(h, lnws, lnbs);

    layer64(h, w1s, b1s);
    lnorm64(h, lnws + 64, lnbs + 64);

    layer64(h, w2s, b2s);
    lnorm64(h, lnws + 128, lnbs + 128);

    float acc = b3s;
#pragma unroll
    for (int k = 0; k < 64; k++) acc += w3s[k] * h[k];
    float y = fmaxf(acc, 0.f);

    if (active) {
        g_y[e] = y;
        atomicAdd(&g_sum_s[src], y);
        atomicAdd(&g_sum_t[dst], y);
    }
}

// ---------------------------------------------------------------------------
__global__ __launch_bounds__(256)
void coef_kernel(const float* __restrict__ x_s, const float* __restrict__ x_t,
                 const int* __restrict__ ei,
                 const float* __restrict__ fw1, const float* __restrict__ fb1,
                 const float* __restrict__ flnw, const float* __restrict__ flnb,
                 const float* __restrict__ fw2, const float* __restrict__ fb2,
                 float* __restrict__ out, int E) {
    __shared__ float fw1s[128], fb1s[32], flnws[32], flnbs[32], fw2s[32];
    __shared__ float fb2s;
    int tid = threadIdx.x;
    if (tid < 128) fw1s[tid] = fw1[tid];
    if (tid < 32) {
        fb1s[tid] = fb1[tid];
        flnws[tid] = flnw[tid];
        flnbs[tid] = flnb[tid];
        fw2s[tid] = fw2[tid];
    }
    if (tid == 0) fb2s = fb2[0];
    __syncthreads();

    int e = blockIdx.x * blockDim.x + tid;
    if (e >= E) return;

    int src = ei[e];
    int dst = ei[E + e];
    float xsd = x_s[src * 2 + 1];
    float xsc = x_t[dst * 2 + 1];
    float ysi = g_sum_s[src];
    float ysj = g_sum_t[dst];

    float h[32];
#pragma unroll
    for (int j = 0; j < 32; j++) {
        float t = fw1s[j * 4] * xsd + fw1s[j * 4 + 1] * ysi +
                  fw1s[j * 4 + 2] * xsc + fw1s[j * 4 + 3] * ysj + fb1s[j];
        h[j] = fmaxf(t, 0.f);
    }
    float s = 0.f;
#pragma unroll
    for (int k = 0; k < 32; k++) s += h[k];
    float m = s * (1.0f / 32.0f);
    float v = 0.f;
#pragma unroll
    for (int k = 0; k < 32; k++) { float d = h[k] - m; v += d * d; }
    v *= (1.0f / 32.0f);
    float inv = rsqrtf(v + EPSLN);

    float acc = fb2s;
#pragma unroll
    for (int k = 0; k < 32; k++) {
        float hn = (h[k] - m) * inv * flnws[k] + flnbs[k];
        acc += fw2s[k] * hn;
    }
    acc = fmaxf(acc, 0.f);
    out[e] = g_y[e] * acc;
}

// ---------------------------------------------------------------------------
extern "C" void kernel_launch(void* const* d_in, const int* in_sizes, int n_in,
                              void* d_out, int out_size) {
    const float* x_s  = (const float*)d_in[0];
    const float* x_t  = (const float*)d_in[1];
    const int*   ei   = (const int*)d_in[2];
    const float* ea   = (const float*)d_in[3];
    const float* w0   = (const float*)d_in[4];
    const float* b0   = (const float*)d_in[5];
    const float* w1   = (const float*)d_in[6];
    const float* b1   = (const float*)d_in[7];
    const float* w2   = (const float*)d_in[8];
    const float* b2   = (const float*)d_in[9];
    const float* w3   = (const float*)d_in[10];
    const float* b3   = (const float*)d_in[11];
    const float* lnw  = (const float*)d_in[12];
    const float* lnb  = (const float*)d_in[13];
    const float* fw1  = (const float*)d_in[14];
    const float* fb1  = (const float*)d_in[15];
    const float* flnw = (const float*)d_in[16];
    const float* flnb = (const float*)d_in[17];
    const float* fw2  = (const float*)d_in[18];
    const float* fb2  = (const float*)d_in[19];

    int E  = in_sizes[3];          // edge_attr element count
    int NS = in_sizes[0] / 2;
    int NT = in_sizes[1] / 2;

    int nmax = NS > NT ? NS : NT;
    zero_kernel<<<(nmax + 255) / 256, 256>>>(NS, NT);

    edge_kernel<<<(E + BLK - 1) / BLK, BLK>>>(
        x_s, x_t, ei, ea, w0, b0, w1, b1, w2, b2, w3, b3, lnw, lnb, E);

    coef_kernel<<<(E + 255) / 256, 256>>>(
        x_s, x_t, ei, fw1, fb1, flnw, flnb, fw2, fb2, (float*)d_out, E);
}

// round 4
// speedup vs baseline: 1.3510x; 1.3510x over previous
#include <cuda_runtime.h>

// ---------------------------------------------------------------------------
// E=2,000,000 edges, N_S=N_T=100,000.
//   k0: zero segment-sum accumulators
//   k1: per-edge MLP (3->64->64->64->1, LeakyReLU+LayerNorm) -> y[e],
//       atomicAdd into sum_s[src], sum_t[dst]
//   k2: coef MLP (4->32->1, ReLU+LayerNorm) -> out[e] = y[e]*coef[e]
// R4: 64x64 layers use packed fma.rn.f32x2 (FFMA2) — halves fma-pipe
//     instruction count vs scalar FFMA. Weights read as 16B LDS.128.
// ---------------------------------------------------------------------------

#define MAX_E  2000000
#define MAX_N  100000
#define EPSLN  1e-5f
#define SLOPE  0.01f

__device__ float g_y[MAX_E];
__device__ float g_sum_s[MAX_N];
__device__ float g_sum_t[MAX_N];

// ---------------------------------------------------------------------------
__global__ void zero_kernel(int ns, int nt) {
    int i = blockIdx.x * blockDim.x + threadIdx.x;
    if (i < ns) g_sum_s[i] = 0.0f;
    if (i < nt) g_sum_t[i] = 0.0f;
}

// ---------------------------------------------------------------------------
// packed f32x2 helpers
typedef unsigned long long u64t;

__device__ __forceinline__ u64t pack2(float lo, float hi) {
    u64t r;
    asm("mov.b64 %0, {%1, %2};" : "=l"(r) : "f"(lo), "f"(hi));
    return r;
}
__device__ __forceinline__ void unpack2(u64t v, float& lo, float& hi) {
    asm("mov.b64 {%0, %1}, %2;" : "=f"(lo), "=f"(hi) : "l"(v));
}
__device__ __forceinline__ u64t ffma2(u64t a, u64t b, u64t c) {
    u64t d;
    asm("fma.rn.f32x2 %0, %1, %2, %3;" : "=l"(d) : "l"(a), "l"(b), "l"(c));
    return d;
}

#define BLK 64

__device__ __forceinline__ void lnorm64(float h[64], const float* __restrict__ w,
                                        const float* __restrict__ b) {
    float s = 0.f;
#pragma unroll
    for (int k = 0; k < 64; k++) s += h[k];
    float m = s * (1.0f / 64.0f);
    float v = 0.f;
#pragma unroll
    for (int k = 0; k < 64; k++) { float d = h[k] - m; v += d * d; }
    v *= (1.0f / 64.0f);
    float inv = rsqrtf(v + EPSLN);
#pragma unroll
    for (int k = 0; k < 64; k++) h[k] = (h[k] - m) * inv * w[k] + b[k];
}

// dense 64x64 + leaky relu. Input: packed h2[32] (k-pairs). Output: scalar g[64].
__device__ __forceinline__ void layer64_packed(const u64t h2[32], float g[64],
                                               const float* __restrict__ W,
                                               const float* __restrict__ b) {
#pragma unroll
    for (int j = 0; j < 64; j++) {
        const ulonglong2* row = (const ulonglong2*)(W + j * 64);  // 16 x 16B
        u64t accA = 0, accB = 0;  // (0.0f,0.0f) packed
#pragma unroll
        for (int k = 0; k < 8; k++) {
            ulonglong2 w0 = row[2 * k];
            ulonglong2 w1 = row[2 * k + 1];
            accA = ffma2(w0.x, h2[4 * k + 0], accA);
            accB = ffma2(w0.y, h2[4 * k + 1], accB);
            accA = ffma2(w1.x, h2[4 * k + 2], accA);
            accB = ffma2(w1.y, h2[4 * k + 3], accB);
        }
        float a0, a1, b0v, b1v;
        unpack2(accA, a0, a1);
        unpack2(accB, b0v, b1v);
        float acc = (a0 + a1) + (b0v + b1v) + b[j];
        g[j] = acc > 0.f ? acc : SLOPE * acc;
    }
}

__global__ __launch_bounds__(BLK)
void edge_kernel(const float* __restrict__ x_s, const float* __restrict__ x_t,
                 const int* __restrict__ ei, const float* __restrict__ ea,
                 const float* __restrict__ w0, const float* __restrict__ b0,
                 const float* __restrict__ w1, const float* __restrict__ b1,
                 const float* __restrict__ w2, const float* __restrict__ b2,
                 const float* __restrict__ w3, const float* __restrict__ b3,
                 const float* __restrict__ lnw, const float* __restrict__ lnb,
                 int E) {
    __shared__ __align__(16) float w1s[4096];   // 16KB
    __shared__ __align__(16) float w2s[4096];   // 16KB
    __shared__ float w0s[192], b0s[64], b1s[64], b2s[64], w3s[64];
    __shared__ float lnws[192], lnbs[192];
    __shared__ float b3s;

    int tid = threadIdx.x;
    for (int i = tid; i < 4096; i += BLK) { w1s[i] = w1[i]; w2s[i] = w2[i]; }
    for (int i = tid; i < 192; i += BLK) { w0s[i] = w0[i]; lnws[i] = lnw[i]; lnbs[i] = lnb[i]; }
    if (tid < 64) { b0s[tid] = b0[tid]; b1s[tid] = b1[tid]; b2s[tid] = b2[tid]; w3s[tid] = w3[tid]; }
    if (tid == 0) b3s = b3[0];
    __syncthreads();

    int e = blockIdx.x * BLK + tid;
    bool active = (e < E);
    int eidx = active ? e : 0;
    int src = ei[eidx];
    int dst = ei[E + eidx];
    float xsd = x_s[src * 2 + 1];
    float xsc = x_t[dst * 2 + 1];
    float att = ea[eidx];

    float h[64];
    // layer0: 3 -> 64 (scalar, tiny)
#pragma unroll
    for (int j = 0; j < 64; j++) {
        float t = w0s[j * 3] * xsd + w0s[j * 3 + 1] * xsc + w0s[j * 3 + 2] * att + b0s[j];
        h[j] = t > 0.f ? t : SLOPE * t;
    }
    lnorm64(h, lnws, lnbs);

    u64t h2[32];
#pragma unroll
    for (int k = 0; k < 32; k++) h2[k] = pack2(h[2 * k], h[2 * k + 1]);

    layer64_packed(h2, h, w1s, b1s);
    lnorm64(h, lnws + 64, lnbs + 64);
#pragma unroll
    for (int k = 0; k < 32; k++) h2[k] = pack2(h[2 * k], h[2 * k + 1]);

    layer64_packed(h2, h, w2s, b2s);
    lnorm64(h, lnws + 128, lnbs + 128);

    float acc = b3s;
#pragma unroll
    for (int k = 0; k < 64; k++) acc += w3s[k] * h[k];
    float y = fmaxf(acc, 0.f);

    if (active) {
        g_y[e] = y;
        atomicAdd(&g_sum_s[src], y);
        atomicAdd(&g_sum_t[dst], y);
    }
}

// ---------------------------------------------------------------------------
__global__ __launch_bounds__(256)
void coef_kernel(const float* __restrict__ x_s, const float* __restrict__ x_t,
                 const int* __restrict__ ei,
                 const float* __restrict__ fw1, const float* __restrict__ fb1,
                 const float* __restrict__ flnw, const float* __restrict__ flnb,
                 const float* __restrict__ fw2, const float* __restrict__ fb2,
                 float* __restrict__ out, int E) {
    __shared__ float fw1s[128], fb1s[32], flnws[32], flnbs[32], fw2s[32];
    __shared__ float fb2s;
    int tid = threadIdx.x;
    if (tid < 128) fw1s[tid] = fw1[tid];
    if (tid < 32) {
        fb1s[tid] = fb1[tid];
        flnws[tid] = flnw[tid];
        flnbs[tid] = flnb[tid];
        fw2s[tid] = fw2[tid];
    }
    if (tid == 0) fb2s = fb2[0];
    __syncthreads();

    int e = blockIdx.x * blockDim.x + tid;
    if (e >= E) return;

    int src = ei[e];
    int dst = ei[E + e];
    float xsd = x_s[src * 2 + 1];
    float xsc = x_t[dst * 2 + 1];
    float ysi = g_sum_s[src];
    float ysj = g_sum_t[dst];

    float h[32];
#pragma unroll
    for (int j = 0; j < 32; j++) {
        float t = fw1s[j * 4] * xsd + fw1s[j * 4 + 1] * ysi +
                  fw1s[j * 4 + 2] * xsc + fw1s[j * 4 + 3] * ysj + fb1s[j];
        h[j] = fmaxf(t, 0.f);
    }
    float s = 0.f;
#pragma unroll
    for (int k = 0; k < 32; k++) s += h[k];
    float m = s * (1.0f / 32.0f);
    float v = 0.f;
#pragma unroll
    for (int k = 0; k < 32; k++) { float d = h[k] - m; v += d * d; }
    v *= (1.0f / 32.0f);
    float inv = rsqrtf(v + EPSLN);

    float acc = fb2s;
#pragma unroll
    for (int k = 0; k < 32; k++) {
        float hn = (h[k] - m) * inv * flnws[k] + flnbs[k];
        acc += fw2s[k] * hn;
    }
    acc = fmaxf(acc, 0.f);
    out[e] = g_y[e] * acc;
}

// ---------------------------------------------------------------------------
extern "C" void kernel_launch(void* const* d_in, const int* in_sizes, int n_in,
                              void* d_out, int out_size) {
    const float* x_s  = (const float*)d_in[0];
    const float* x_t  = (const float*)d_in[1];
    const int*   ei   = (const int*)d_in[2];
    const float* ea   = (const float*)d_in[3];
    const float* w0   = (const float*)d_in[4];
    const float* b0   = (const float*)d_in[5];
    const float* w1   = (const float*)d_in[6];
    const float* b1   = (const float*)d_in[7];
    const float* w2   = (const float*)d_in[8];
    const float* b2   = (const float*)d_in[9];
    const float* w3   = (const float*)d_in[10];
    const float* b3   = (const float*)d_in[11];
    const float* lnw  = (const float*)d_in[12];
    const float* lnb  = (const float*)d_in[13];
    const float* fw1  = (const float*)d_in[14];
    const float* fb1  = (const float*)d_in[15];
    const float* flnw = (const float*)d_in[16];
    const float* flnb = (const float*)d_in[17];
    const float* fw2  = (const float*)d_in[18];
    const float* fb2  = (const float*)d_in[19];

    int E  = in_sizes[3];          // edge_attr element count
    int NS = in_sizes[0] / 2;
    int NT = in_sizes[1] / 2;

    int nmax = NS > NT ? NS : NT;
    zero_kernel<<<(nmax + 255) / 256, 256>>>(NS, NT);

    edge_kernel<<<(E + BLK - 1) / BLK, BLK>>>(
        x_s, x_t, ei, ea, w0, b0, w1, b1, w2, b2, w3, b3, lnw, lnb, E);

    coef_kernel<<<(E + 255) / 256, 256>>>(
        x_s, x_t, ei, fw1, fb1, flnw, flnb, fw2, fb2, (float*)d_out, E);
}

// round 7
// speedup vs baseline: 2.3877x; 1.7673x over previous
#include <cuda_runtime.h>
#include <cstdint>

// ---------------------------------------------------------------------------
// E=2,000,000 edges, N_S=N_T=100,000.
//   k0: zero segment-sum accumulators
//   k1: edge MLP; 64x64 layers via warp-level mma.sync tf32 (m16n8k8) with
//       3xTF32 precision split (fp32-equivalent). Hidden tile in SMEM as fp32
//       (pair-permuted); weights as hi/lo tf32 pairs. LeakyReLU+LayerNorm
//       per-thread in registers.
//   k2: coef MLP (4->32->1) scalar.
// ---------------------------------------------------------------------------

#define MAX_E  2000000
#define MAX_N  100000
#define EPSLN  1e-5f
#define SLOPE  0.01f

__device__ float g_y[MAX_E];
__device__ float g_sum_s[MAX_N];
__device__ float g_sum_t[MAX_N];

// ---------------------------------------------------------------------------
__global__ void zero_kernel(int ns, int nt) {
    int i = blockIdx.x * blockDim.x + threadIdx.x;
    if (i < ns) g_sum_s[i] = 0.0f;
    if (i < nt) g_sum_t[i] = 0.0f;
}

// ---------------------------------------------------------------------------
__device__ __forceinline__ uint32_t smem_u32(const void* p) {
    uint32_t a;
    asm("{ .reg .u64 t; cvta.to.shared.u64 t, %1; cvt.u32.u64 %0, t; }"
        : "=r"(a) : "l"(p));
    return a;
}
__device__ __forceinline__ uint32_t f2tf32(float x) {
    uint32_t r;
    asm("cvt.rna.tf32.f32 %0, %1;" : "=r"(r) : "f"(x));
    return r;
}
__device__ __forceinline__ void lds_v2_u(uint32_t addr, uint32_t& x, uint32_t& y) {
    asm volatile("ld.shared.v2.b32 {%0,%1}, [%2];" : "=r"(x), "=r"(y) : "r"(addr));
}
__device__ __forceinline__ void lds_v2_f(uint32_t addr, float& x, float& y) {
    asm volatile("ld.shared.v2.f32 {%0,%1}, [%2];" : "=f"(x), "=f"(y) : "r"(addr));
}
__device__ __forceinline__ void sts_v2_f(uint32_t addr, float x, float y) {
    asm volatile("st.shared.v2.f32 [%0], {%1,%2};" :: "r"(addr), "f"(x), "f"(y));
}
__device__ __forceinline__ void mma_tf32(float d[4], uint32_t a0, uint32_t a1,
                                         uint32_t a2, uint32_t a3,
                                         uint32_t b0, uint32_t b1) {
    asm volatile(
        "mma.sync.aligned.m16n8k8.row.col.f32.tf32.tf32.f32 "
        "{%0,%1,%2,%3}, {%4,%5,%6,%7}, {%8,%9}, {%0,%1,%2,%3};"
        : "+f"(d[0]), "+f"(d[1]), "+f"(d[2]), "+f"(d[3])
        : "r"(a0), "r"(a1), "r"(a2), "r"(a3), "r"(b0), "r"(b1));
}

// ---------------------------------------------------------------------------
#define TB     128
#define TILE   128
#define RS     66          // smem row stride in floats (padded)
#define T_OFF   0
#define WTILE   (64 * RS * 4)
#define W1H_OFF (128 * RS * 4)
#define W1L_OFF (W1H_OFF + WTILE)
#define W2H_OFF (W1L_OFF + WTILE)
#define W2L_OFF (W2H_OFF + WTILE)
#define DYN_SMEM (W2L_OFF + WTILE)   // 33792 + 4*16896 = 101376 B

__device__ __forceinline__ void lnorm64(float h[64], const float* __restrict__ w,
                                        const float* __restrict__ b) {
    float s = 0.f;
#pragma unroll
    for (int k = 0; k < 64; k++) s += h[k];
    float m = s * (1.0f / 64.0f);
    float v = 0.f;
#pragma unroll
    for (int k = 0; k < 64; k++) { float d = h[k] - m; v += d * d; }
    v *= (1.0f / 64.0f);
    float inv = rsqrtf(v + EPSLN);
#pragma unroll
    for (int k = 0; k < 64; k++) h[k] = (h[k] - m) * inv * w[k] + b[k];
}

// Write this thread's row (pair-permuted, fp32): pos 8g+2i <- h[8g+i], 8g+2i+1 <- h[8g+i+4]
__device__ __forceinline__ void store_row_permuted(uint32_t tbase, int row, const float h[64]) {
    uint32_t rb = tbase + (uint32_t)(row * RS) * 4u;
#pragma unroll
    for (int g = 0; g < 8; g++) {
#pragma unroll
        for (int i = 0; i < 4; i++) {
            sts_v2_f(rb + (uint32_t)(8 * g + 2 * i) * 4u, h[8 * g + i], h[8 * g + i + 4]);
        }
    }
}

// One 64x64 layer via 3xTF32 mma. A rows [32*warp, 32*warp+32) of T (fp32,
// permuted); B from Whi/Wlo (tf32, permuted). D written back to T (natural order).
__device__ __forceinline__ void mma_layer(uint32_t tbase, uint32_t whbase, uint32_t wlbase,
                                          int warp, int lane) {
    int qrow = lane >> 2, qc = lane & 3;
    float acc[2][8][4];
#pragma unroll
    for (int mt = 0; mt < 2; mt++)
#pragma unroll
        for (int n = 0; n < 8; n++)
#pragma unroll
            for (int f = 0; f < 4; f++) acc[mt][n][f] = 0.f;

#pragma unroll
    for (int s = 0; s < 8; s++) {
        uint32_t ahi[2][4], alo[2][4];
#pragma unroll
        for (int mt = 0; mt < 2; mt++) {
            float a0, a1, a2, a3;
            uint32_t r0 = tbase + (uint32_t)((32 * warp + 16 * mt + qrow) * RS + 8 * s + 2 * qc) * 4u;
            lds_v2_f(r0, a0, a2);
            lds_v2_f(r0 + (uint32_t)(8 * RS) * 4u, a1, a3);
            ahi[mt][0] = f2tf32(a0); alo[mt][0] = f2tf32(a0 - __uint_as_float(ahi[mt][0]));
            ahi[mt][1] = f2tf32(a1); alo[mt][1] = f2tf32(a1 - __uint_as_float(ahi[mt][1]));
            ahi[mt][2] = f2tf32(a2); alo[mt][2] = f2tf32(a2 - __uint_as_float(ahi[mt][2]));
            ahi[mt][3] = f2tf32(a3); alo[mt][3] = f2tf32(a3 - __uint_as_float(ahi[mt][3]));
        }
#pragma unroll
        for (int n = 0; n < 8; n++) {
            uint32_t bh0, bh1, bl0, bl1;
            uint32_t boff = (uint32_t)((8 * n + qrow) * RS + 8 * s + 2 * qc) * 4u;
            lds_v2_u(whbase + boff, bh0, bh1);
            lds_v2_u(wlbase + boff, bl0, bl1);
#pragma unroll
            for (int mt = 0; mt < 2; mt++) {
                mma_tf32(acc[mt][n], ahi[mt][0], ahi[mt][1], ahi[mt][2], ahi[mt][3], bh0, bh1);
                mma_tf32(acc[mt][n], alo[mt][0], alo[mt][1], alo[mt][2], alo[mt][3], bh0, bh1);
                mma_tf32(acc[mt][n], ahi[mt][0], ahi[mt][1], ahi[mt][2], ahi[mt][3], bl0, bl1);
            }
        }
    }
    __syncwarp();
    // write D back in natural order
#pragma unroll
    for (int mt = 0; mt < 2; mt++) {
        uint32_t rd = tbase + (uint32_t)((32 * warp + 16 * mt + qrow) * RS) * 4u;
#pragma unroll
        for (int n = 0; n < 8; n++) {
            uint32_t off = (uint32_t)(8 * n + 2 * qc) * 4u;
            sts_v2_f(rd + off, acc[mt][n][0], acc[mt][n][1]);
            sts_v2_f(rd + (uint32_t)(8 * RS) * 4u + off, acc[mt][n][2], acc[mt][n][3]);
        }
    }
    __syncwarp();
}

__global__ __launch_bounds__(TB)
void edge_kernel(const float* __restrict__ x_s, const float* __restrict__ x_t,
                 const int* __restrict__ ei, const float* __restrict__ ea,
                 const float* __restrict__ w0, const float* __restrict__ b0,
                 const float* __restrict__ w1, const float* __restrict__ b1,
                 const float* __restrict__ w2, const float* __restrict__ b2,
                 const float* __restrict__ w3, const float* __restrict__ b3,
                 const float* __restrict__ lnw, const float* __restrict__ lnb,
                 int E) {
    extern __shared__ __align__(16) char dsm[];
    uint32_t dbase = smem_u32(dsm);
    uint32_t tbase   = dbase + T_OFF;
    uint32_t w1hbase = dbase + W1H_OFF;
    uint32_t w1lbase = dbase + W1L_OFF;
    uint32_t w2hbase = dbase + W2H_OFF;
    uint32_t w2lbase = dbase + W2L_OFF;

    __shared__ float w0s[192], b0s[64], b1s[64], b2s[64], w3s[64];
    __shared__ float lnws[192], lnbs[192];
    __shared__ float b3s;

    int tid = threadIdx.x;
    int warp = tid >> 5, lane = tid & 31;

    // weights -> smem, pair-permuted tf32 hi/lo split.
    for (int i = tid; i < 4096; i += TB) {
        int row = i >> 6, col = i & 63;
        int g = col >> 3, c = col & 7;
        int pos = 8 * g + ((c < 4) ? (2 * c) : (2 * (c - 4) + 1));
        uint32_t off = (uint32_t)(row * RS + pos) * 4u;
        float v1 = w1[i], v2 = w2[i];
        uint32_t v1h = f2tf32(v1), v2h = f2tf32(v2);
        uint32_t v1l = f2tf32(v1 - __uint_as_float(v1h));
        uint32_t v2l = f2tf32(v2 - __uint_as_float(v2h));
        asm volatile("st.shared.b32 [%0], %1;" :: "r"(w1hbase + off), "r"(v1h));
        asm volatile("st.shared.b32 [%0], %1;" :: "r"(w1lbase + off), "r"(v1l));
        asm volatile("st.shared.b32 [%0], %1;" :: "r"(w2hbase + off), "r"(v2h));
        asm volatile("st.shared.b32 [%0], %1;" :: "r"(w2lbase + off), "r"(v2l));
    }
    for (int i = tid; i < 192; i += TB) { w0s[i] = w0[i]; lnws[i] = lnw[i]; lnbs[i] = lnb[i]; }
    if (tid < 64) { b0s[tid] = b0[tid]; b1s[tid] = b1[tid]; b2s[tid] = b2[tid]; w3s[tid] = w3[tid]; }
    if (tid == 0) b3s = b3[0];
    __syncthreads();

    // gather + layer0 (3->64)
    int e = blockIdx.x * TILE + tid;
    bool active = (e < E);
    int eidx = active ? e : (E - 1);
    int src = ei[eidx];
    int dst = ei[E + eidx];
    float xsd = x_s[src * 2 + 1];
    float xsc = x_t[dst * 2 + 1];
    float att = ea[eidx];

    float h[64];
#pragma unroll
    for (int j = 0; j < 64; j++) {
        float t = w0s[j * 3] * xsd + w0s[j * 3 + 1] * xsc + w0s[j * 3 + 2] * att + b0s[j];
        h[j] = t > 0.f ? t : SLOPE * t;
    }
    lnorm64(h, lnws, lnbs);

    // ---- layer 1 ----
    store_row_permuted(tbase, tid, h);
    __syncwarp();
    mma_layer(tbase, w1hbase, w1lbase, warp, lane);
    {
        uint32_t rb = tbase + (uint32_t)(tid * RS) * 4u;
#pragma unroll
        for (int j = 0; j < 32; j++) {
            float a, b;
            lds_v2_f(rb + (uint32_t)(2 * j) * 4u, a, b);
            float t0 = a + b1s[2 * j];
            float t1 = b + b1s[2 * j + 1];
            h[2 * j]     = t0 > 0.f ? t0 : SLOPE * t0;
            h[2 * j + 1] = t1 > 0.f ? t1 : SLOPE * t1;
        }
    }
    lnorm64(h, lnws + 64, lnbs + 64);

    // ---- layer 2 ----
    __syncwarp();
    store_row_permuted(tbase, tid, h);
    __syncwarp();
    mma_layer(tbase, w2hbase, w2lbase, warp, lane);
    {
        uint32_t rb = tbase + (uint32_t)(tid * RS) * 4u;
#pragma unroll
        for (int j = 0; j < 32; j++) {
            float a, b;
            lds_v2_f(rb + (uint32_t)(2 * j) * 4u, a, b);
            float t0 = a + b2s[2 * j];
            float t1 = b + b2s[2 * j + 1];
            h[2 * j]     = t0 > 0.f ? t0 : SLOPE * t0;
            h[2 * j + 1] = t1 > 0.f ? t1 : SLOPE * t1;
        }
    }
    lnorm64(h, lnws + 128, lnbs + 128);

    // ---- final dot 64->1, relu, scatter ----
    float acc = b3s;
#pragma unroll
    for (int k = 0; k < 64; k++) acc += w3s[k] * h[k];
    float y = fmaxf(acc, 0.f);

    if (active) {
        g_y[e] = y;
        atomicAdd(&g_sum_s[src], y);
        atomicAdd(&g_sum_t[dst], y);
    }
}

// ---------------------------------------------------------------------------
__global__ __launch_bounds__(256)
void coef_kernel(const float* __restrict__ x_s, const float* __restrict__ x_t,
                 const int* __restrict__ ei,
                 const float* __restrict__ fw1, const float* __restrict__ fb1,
                 const float* __restrict__ flnw, const float* __restrict__ flnb,
                 const float* __restrict__ fw2, const float* __restrict__ fb2,
                 float* __restrict__ out, int E) {
    __shared__ float fw1s[128], fb1s[32], flnws[32], flnbs[32], fw2s[32];
    __shared__ float fb2s;
    int tid = threadIdx.x;
    if (tid < 128) fw1s[tid] = fw1[tid];
    if (tid < 32) {
        fb1s[tid] = fb1[tid];
        flnws[tid] = flnw[tid];
        flnbs[tid] = flnb[tid];
        fw2s[tid] = fw2[tid];
    }
    if (tid == 0) fb2s = fb2[0];
    __syncthreads();

    int e = blockIdx.x * blockDim.x + tid;
    if (e >= E) return;

    int src = ei[e];
    int dst = ei[E + e];
    float xsd = x_s[src * 2 + 1];
    float xsc = x_t[dst * 2 + 1];
    float ysi = g_sum_s[src];
    float ysj = g_sum_t[dst];

    float h[32];
#pragma unroll
    for (int j = 0; j < 32; j++) {
        float t = fw1s[j * 4] * xsd + fw1s[j * 4 + 1] * ysi +
                  fw1s[j * 4 + 2] * xsc + fw1s[j * 4 + 3] * ysj + fb1s[j];
        h[j] = fmaxf(t, 0.f);
    }
    float s = 0.f;
#pragma unroll
    for (int k = 0; k < 32; k++) s += h[k];
    float m = s * (1.0f / 32.0f);
    float v = 0.f;
#pragma unroll
    for (int k = 0; k < 32; k++) { float d = h[k] - m; v += d * d; }
    v *= (1.0f / 32.0f);
    float inv = rsqrtf(v + EPSLN);

    float acc = fb2s;
#pragma unroll
    for (int k = 0; k < 32; k++) {
        float hn = (h[k] - m) * inv * flnws[k] + flnbs[k];
        acc += fw2s[k] * hn;
    }
    acc = fmaxf(acc, 0.f);
    out[e] = g_y[e] * acc;
}

// ---------------------------------------------------------------------------
extern "C" void kernel_launch(void* const* d_in, const int* in_sizes, int n_in,
                              void* d_out, int out_size) {
    const float* x_s  = (const float*)d_in[0];
    const float* x_t  = (const float*)d_in[1];
    const int*   ei   = (const int*)d_in[2];
    const float* ea   = (const float*)d_in[3];
    const float* w0   = (const float*)d_in[4];
    const float* b0   = (const float*)d_in[5];
    const float* w1   = (const float*)d_in[6];
    const float* b1   = (const float*)d_in[7];
    const float* w2   = (const float*)d_in[8];
    const float* b2   = (const float*)d_in[9];
    const float* w3   = (const float*)d_in[10];
    const float* b3   = (const float*)d_in[11];
    const float* lnw  = (const float*)d_in[12];
    const float* lnb  = (const float*)d_in[13];
    const float* fw1  = (const float*)d_in[14];
    const float* fb1  = (const float*)d_in[15];
    const float* flnw = (const float*)d_in[16];
    const float* flnb = (const float*)d_in[17];
    const float* fw2  = (const float*)d_in[18];
    const float* fb2  = (const float*)d_in[19];

    int E  = in_sizes[3];
    int NS = in_sizes[0] / 2;
    int NT = in_sizes[1] / 2;

    int nmax = NS > NT ? NS : NT;
    zero_kernel<<<(nmax + 255) / 256, 256>>>(NS, NT);

    cudaFuncSetAttribute(edge_kernel, cudaFuncAttributeMaxDynamicSharedMemorySize, DYN_SMEM);

    edge_kernel<<<(E + TILE - 1) / TILE, TB, DYN_SMEM>>>(
        x_s, x_t, ei, ea, w0, b0, w1, b1, w2, b2, w3, b3, lnw, lnb, E);

    coef_kernel<<<(E + 255) / 256, 256>>>(
        x_s, x_t, ei, fw1, fb1, flnw, flnb, fw2, fb2, (float*)d_out, E);
}

// round 8
// speedup vs baseline: 3.2733x; 1.3709x over previous
#include <cuda_runtime.h>
#include <cuda_fp16.h>
#include <cstdint>

// ---------------------------------------------------------------------------
// E=2,000,000 edges, N_S=N_T=100,000.
//   k0: zero segment-sum accumulators
//   k1: edge MLP; 64x64 layers via warp-level mma.sync m16n8k16 fp16 with
//       3-term hi/lo split (fp32-equivalent ~22 bits). Hidden tile in
//       per-warp SMEM planes (f16x2 hi + lo); D written back fp32.
//   k2: coef MLP (4->32->1) scalar.
// ---------------------------------------------------------------------------

#define MAX_E  2000000
#define MAX_N  100000
#define EPSLN  1e-5f
#define SLOPE  0.01f

__device__ float g_y[MAX_E];
__device__ float g_sum_s[MAX_N];
__device__ float g_sum_t[MAX_N];

// ---------------------------------------------------------------------------
__global__ void zero_kernel(int ns, int nt) {
    int i = blockIdx.x * blockDim.x + threadIdx.x;
    if (i < ns) g_sum_s[i] = 0.0f;
    if (i < nt) g_sum_t[i] = 0.0f;
}

// ---------------------------------------------------------------------------
__device__ __forceinline__ uint32_t smem_u32(const void* p) {
    uint32_t a;
    asm("{ .reg .u64 t; cvta.to.shared.u64 t, %1; cvt.u32.u64 %0, t; }"
        : "=r"(a) : "l"(p));
    return a;
}
__device__ __forceinline__ void lds_v2_u(uint32_t addr, uint32_t& x, uint32_t& y) {
    asm volatile("ld.shared.v2.b32 {%0,%1}, [%2];" : "=r"(x), "=r"(y) : "r"(addr));
}
__device__ __forceinline__ void lds_v2_f(uint32_t addr, float& x, float& y) {
    asm volatile("ld.shared.v2.f32 {%0,%1}, [%2];" : "=f"(x), "=f"(y) : "r"(addr));
}
__device__ __forceinline__ void sts_v2_u(uint32_t addr, uint32_t x, uint32_t y) {
    asm volatile("st.shared.v2.b32 [%0], {%1,%2};" :: "r"(addr), "r"(x), "r"(y));
}
__device__ __forceinline__ void sts_v2_f(uint32_t addr, float x, float y) {
    asm volatile("st.shared.v2.f32 [%0], {%1,%2};" :: "r"(addr), "f"(x), "f"(y));
}
__device__ __forceinline__ void sts_b32(uint32_t addr, uint32_t v) {
    asm volatile("st.shared.b32 [%0], %1;" :: "r"(addr), "r"(v));
}
__device__ __forceinline__ void mma_f16(float d[4], uint32_t a0, uint32_t a1,
                                        uint32_t a2, uint32_t a3,
                                        uint32_t b0, uint32_t b1) {
    asm volatile(
        "mma.sync.aligned.m16n8k16.row.col.f32.f16.f16.f32 "
        "{%0,%1,%2,%3}, {%4,%5,%6,%7}, {%8,%9}, {%0,%1,%2,%3};"
        : "+f"(d[0]), "+f"(d[1]), "+f"(d[2]), "+f"(d[3])
        : "r"(a0), "r"(a1), "r"(a2), "r"(a3), "r"(b0), "r"(b1));
}

// split two f32 values (consecutive k, k+1) into hi/lo f16x2 packs
__device__ __forceinline__ void split2(float x0, float x1, uint32_t& hi, uint32_t& lo) {
    __half2 h = __floats2half2_rn(x0, x1);      // .x (low half) = x0 -> element k
    hi = *reinterpret_cast<uint32_t*>(&h);
    float2 hf = __half22float2(h);
    __half2 l = __floats2half2_rn(x0 - hf.x, x1 - hf.y);
    lo = *reinterpret_cast<uint32_t*>(&l);
}

// ---------------------------------------------------------------------------
#define TB     128
#define TILE   128
#define PSB    136u            // f16x2 plane row stride (34 b32 words)
#define PLANE  4352u           // 32 rows * 136
#define WREG   8704u           // per-warp T region: hi + lo plane
#define DSTR   264u            // fp32 D row stride (66 words), overlays planes
#define T_BYTES   (4u * WREG)          // 34816
#define WPLANE    8704u                // 64 rows * 136
#define W_OFF     T_BYTES
#define DYN_SMEM  (T_BYTES + 4u * WPLANE)   // 69632 B

// slot within a row for b32-pair index p (0..31): s-block 8s, inner i
__device__ __forceinline__ uint32_t pair_slot(int p) {
    int s = p >> 3, i = p & 7;
    return (uint32_t)(8 * s + ((i < 4) ? (2 * i) : (2 * (i - 4) + 1)));
}

__device__ __forceinline__ void lnorm64(float h[64], const float* __restrict__ w,
                                        const float* __restrict__ b) {
    float s = 0.f;
#pragma unroll
    for (int k = 0; k < 64; k++) s += h[k];
    float m = s * (1.0f / 64.0f);
    float v = 0.f;
#pragma unroll
    for (int k = 0; k < 64; k++) { float d = h[k] - m; v += d * d; }
    v *= (1.0f / 64.0f);
    float inv = rsqrtf(v + EPSLN);
#pragma unroll
    for (int k = 0; k < 64; k++) h[k] = (h[k] - m) * inv * w[k] + b[k];
}

// Store this thread's row into its warp's hi/lo f16x2 planes.
__device__ __forceinline__ void store_row_f16(uint32_t region, int rloc, const float h[64]) {
    uint32_t rb = region + (uint32_t)rloc * PSB;
#pragma unroll
    for (int s = 0; s < 4; s++) {
#pragma unroll
        for (int i = 0; i < 4; i++) {
            int pa = 8 * s + i, pb = pa + 4;
            uint32_t hiA, loA, hiB, loB;
            split2(h[2 * pa], h[2 * pa + 1], hiA, loA);
            split2(h[2 * pb], h[2 * pb + 1], hiB, loB);
            uint32_t off = (uint32_t)(8 * s + 2 * i) * 4u;
            sts_v2_u(rb + off, hiA, hiB);
            sts_v2_u(rb + PLANE + off, loA, loB);
        }
    }
}

// One 64x64 layer: A from warp-private hi/lo planes, B from weight hi/lo
// planes, 3-term fp16 MMA, D written back fp32 (stride DSTR) into region.
__device__ __forceinline__ void mma_layer(uint32_t region, uint32_t wh, uint32_t wl,
                                          int lane) {
    int qrow = lane >> 2, qc = lane & 3;
    float acc[2][8][4];
#pragma unroll
    for (int mt = 0; mt < 2; mt++)
#pragma unroll
        for (int n = 0; n < 8; n++)
#pragma unroll
            for (int f = 0; f < 4; f++) acc[mt][n][f] = 0.f;

#pragma unroll
    for (int s = 0; s < 4; s++) {
        uint32_t Ah[2][4], Al[2][4];
#pragma unroll
        for (int mt = 0; mt < 2; mt++) {
            uint32_t r0 = region + (uint32_t)(16 * mt + qrow) * PSB
                        + (uint32_t)(8 * s + 2 * qc) * 4u;
            lds_v2_u(r0,             Ah[mt][0], Ah[mt][2]);
            lds_v2_u(r0 + 8u * PSB,  Ah[mt][1], Ah[mt][3]);
            lds_v2_u(r0 + PLANE,             Al[mt][0], Al[mt][2]);
            lds_v2_u(r0 + PLANE + 8u * PSB,  Al[mt][1], Al[mt][3]);
        }
#pragma unroll
        for (int n = 0; n < 8; n++) {
            uint32_t bh0, bh1, bl0, bl1;
            uint32_t ba = (uint32_t)(8 * n + qrow) * PSB + (uint32_t)(8 * s + 2 * qc) * 4u;
            lds_v2_u(wh + ba, bh0, bh1);
            lds_v2_u(wl + ba, bl0, bl1);
#pragma unroll
            for (int mt = 0; mt < 2; mt++) {
                mma_f16(acc[mt][n], Ah[mt][0], Ah[mt][1], Ah[mt][2], Ah[mt][3], bh0, bh1);
                mma_f16(acc[mt][n], Al[mt][0], Al[mt][1], Al[mt][2], Al[mt][3], bh0, bh1);
                mma_f16(acc[mt][n], Ah[mt][0], Ah[mt][1], Ah[mt][2], Ah[mt][3], bl0, bl1);
            }
        }
    }
    __syncwarp();
    // D writeback, fp32, natural order (overlays planes; A fully consumed)
#pragma unroll
    for (int mt = 0; mt < 2; mt++) {
        uint32_t rd = region + (uint32_t)(16 * mt + qrow) * DSTR;
#pragma unroll
        for (int n = 0; n < 8; n++) {
            uint32_t off = (uint32_t)(8 * n + 2 * qc) * 4u;
            sts_v2_f(rd + off, acc[mt][n][0], acc[mt][n][1]);
            sts_v2_f(rd + 8u * DSTR + off, acc[mt][n][2], acc[mt][n][3]);
        }
    }
    __syncwarp();
}

__global__ __launch_bounds__(TB)
void edge_kernel(const float* __restrict__ x_s, const float* __restrict__ x_t,
                 const int* __restrict__ ei, const float* __restrict__ ea,
                 const float* __restrict__ w0, const float* __restrict__ b0,
                 const float* __restrict__ w1, const float* __restrict__ b1,
                 const float* __restrict__ w2, const float* __restrict__ b2,
                 const float* __restrict__ w3, const float* __restrict__ b3,
                 const float* __restrict__ lnw, const float* __restrict__ lnb,
                 int E) {
    extern __shared__ __align__(16) char dsm[];
    uint32_t dbase = smem_u32(dsm);
    uint32_t w1h = dbase + W_OFF;
    uint32_t w1l = w1h + WPLANE;
    uint32_t w2h = w1l + WPLANE;
    uint32_t w2l = w2h + WPLANE;

    __shared__ float w0s[192], b0s[64], b1s[64], b2s[64], w3s[64];
    __shared__ float lnws[192], lnbs[192];
    __shared__ float b3s;

    int tid = threadIdx.x;
    int warp = tid >> 5, lane = tid & 31;
    uint32_t region = dbase + (uint32_t)warp * WREG;

    // weights -> hi/lo f16x2 planes (by b32-pair)
    {
        const float2* w1v = (const float2*)w1;
        const float2* w2v = (const float2*)w2;
        for (int q = tid; q < 2048; q += TB) {
            int row = q >> 5, p = q & 31;
            uint32_t off = (uint32_t)row * PSB + pair_slot(p) * 4u;
            float2 a = w1v[q];
            uint32_t hi, lo;
            split2(a.x, a.y, hi, lo);
            sts_b32(w1h + off, hi);
            sts_b32(w1l + off, lo);
            float2 c = w2v[q];
            split2(c.x, c.y, hi, lo);
            sts_b32(w2h + off, hi);
            sts_b32(w2l + off, lo);
        }
    }
    for (int i = tid; i < 192; i += TB) { w0s[i] = w0[i]; lnws[i] = lnw[i]; lnbs[i] = lnb[i]; }
    if (tid < 64) { b0s[tid] = b0[tid]; b1s[tid] = b1[tid]; b2s[tid] = b2[tid]; w3s[tid] = w3[tid]; }
    if (tid == 0) b3s = b3[0];
    __syncthreads();

    // gather + layer0 (3->64)
    int e = blockIdx.x * TILE + tid;
    bool active = (e < E);
    int eidx = active ? e : (E - 1);
    int src = ei[eidx];
    int dst = ei[E + eidx];
    float xsd = x_s[src * 2 + 1];
    float xsc = x_t[dst * 2 + 1];
    float att = ea[eidx];

    float h[64];
#pragma unroll
    for (int j = 0; j < 64; j++) {
        float t = w0s[j * 3] * xsd + w0s[j * 3 + 1] * xsc + w0s[j * 3 + 2] * att + b0s[j];
        h[j] = t > 0.f ? t : SLOPE * t;
    }
    lnorm64(h, lnws, lnbs);

    // ---- layer 1 ----
    store_row_f16(region, lane, h);
    __syncwarp();
    mma_layer(region, w1h, w1l, lane);
    {
        uint32_t rb = region + (uint32_t)lane * DSTR;
#pragma unroll
        for (int j = 0; j < 32; j++) {
            float a, b;
            lds_v2_f(rb + (uint32_t)(2 * j) * 4u, a, b);
            float t0 = a + b1s[2 * j];
            float t1 = b + b1s[2 * j + 1];
            h[2 * j]     = t0 > 0.f ? t0 : SLOPE * t0;
            h[2 * j + 1] = t1 > 0.f ? t1 : SLOPE * t1;
        }
    }
    lnorm64(h, lnws + 64, lnbs + 64);

    // ---- layer 2 ----
    __syncwarp();
    store_row_f16(region, lane, h);
    __syncwarp();
    mma_layer(region, w2h, w2l, lane);
    {
        uint32_t rb = region + (uint32_t)lane * DSTR;
#pragma unroll
        for (int j = 0; j < 32; j++) {
            float a, b;
            lds_v2_f(rb + (uint32_t)(2 * j) * 4u, a, b);
            float t0 = a + b2s[2 * j];
            float t1 = b + b2s[2 * j + 1];
            h[2 * j]     = t0 > 0.f ? t0 : SLOPE * t0;
            h[2 * j + 1] = t1 > 0.f ? t1 : SLOPE * t1;
        }
    }
    lnorm64(h, lnws + 128, lnbs + 128);

    // ---- final dot 64->1, relu, scatter ----
    float acc = b3s;
#pragma unroll
    for (int k = 0; k < 64; k++) acc += w3s[k] * h[k];
    float y = fmaxf(acc, 0.f);

    if (active) {
        g_y[e] = y;
        atomicAdd(&g_sum_s[src], y);
        atomicAdd(&g_sum_t[dst], y);
    }
}

// ---------------------------------------------------------------------------
__global__ __launch_bounds__(256)
void coef_kernel(const float* __restrict__ x_s, const float* __restrict__ x_t,
                 const int* __restrict__ ei,
                 const float* __restrict__ fw1, const float* __restrict__ fb1,
                 const float* __restrict__ flnw, const float* __restrict__ flnb,
                 const float* __restrict__ fw2, const float* __restrict__ fb2,
                 float* __restrict__ out, int E) {
    __shared__ float fw1s[128], fb1s[32], flnws[32], flnbs[32], fw2s[32];
    __shared__ float fb2s;
    int tid = threadIdx.x;
    if (tid < 128) fw1s[tid] = fw1[tid];
    if (tid < 32) {
        fb1s[tid] = fb1[tid];
        flnws[tid] = flnw[tid];
        flnbs[tid] = flnb[tid];
        fw2s[tid] = fw2[tid];
    }
    if (tid == 0) fb2s = fb2[0];
    __syncthreads();

    int e = blockIdx.x * blockDim.x + tid;
    if (e >= E) return;

    int src = ei[e];
    int dst = ei[E + e];
    float xsd = x_s[src * 2 + 1];
    float xsc = x_t[dst * 2 + 1];
    float ysi = g_sum_s[src];
    float ysj = g_sum_t[dst];

    float h[32];
#pragma unroll
    for (int j = 0; j < 32; j++) {
        float t = fw1s[j * 4] * xsd + fw1s[j * 4 + 1] * ysi +
                  fw1s[j * 4 + 2] * xsc + fw1s[j * 4 + 3] * ysj + fb1s[j];
        h[j] = fmaxf(t, 0.f);
    }
    float s = 0.f;
#pragma unroll
    for (int k = 0; k < 32; k++) s += h[k];
    float m = s * (1.0f / 32.0f);
    float v = 0.f;
#pragma unroll
    for (int k = 0; k < 32; k++) { float d = h[k] - m; v += d * d; }
    v *= (1.0f / 32.0f);
    float inv = rsqrtf(v + EPSLN);

    float acc = fb2s;
#pragma unroll
    for (int k = 0; k < 32; k++) {
        float hn = (h[k] - m) * inv * flnws[k] + flnbs[k];
        acc += fw2s[k] * hn;
    }
    acc = fmaxf(acc, 0.f);
    out[e] = g_y[e] * acc;
}

// ---------------------------------------------------------------------------
extern "C" void kernel_launch(void* const* d_in, const int* in_sizes, int n_in,
                              void* d_out, int out_size) {
    const float* x_s  = (const float*)d_in[0];
    const float* x_t  = (const float*)d_in[1];
    const int*   ei   = (const int*)d_in[2];
    const float* ea   = (const float*)d_in[3];
    const float* w0   = (const float*)d_in[4];
    const float* b0   = (const float*)d_in[5];
    const float* w1   = (const float*)d_in[6];
    const float* b1   = (const float*)d_in[7];
    const float* w2   = (const float*)d_in[8];
    const float* b2   = (const float*)d_in[9];
    const float* w3   = (const float*)d_in[10];
    const float* b3   = (const float*)d_in[11];
    const float* lnw  = (const float*)d_in[12];
    const float* lnb  = (const float*)d_in[13];
    const float* fw1  = (const float*)d_in[14];
    const float* fb1  = (const float*)d_in[15];
    const float* flnw = (const float*)d_in[16];
    const float* flnb = (const float*)d_in[17];
    const float* fw2  = (const float*)d_in[18];
    const float* fb2  = (const float*)d_in[19];

    int E  = in_sizes[3];
    int NS = in_sizes[0] / 2;
    int NT = in_sizes[1] / 2;

    int nmax = NS > NT ? NS : NT;
    zero_kernel<<<(nmax + 255) / 256, 256>>>(NS, NT);

    cudaFuncSetAttribute(edge_kernel, cudaFuncAttributeMaxDynamicSharedMemorySize, DYN_SMEM);

    edge_kernel<<<(E + TILE - 1) / TILE, TB, DYN_SMEM>>>(
        x_s, x_t, ei, ea, w0, b0, w1, b1, w2, b2, w3, b3, lnw, lnb, E);

    coef_kernel<<<(E + 255) / 256, 256>>>(
        x_s, x_t, ei, fw1, fb1, flnw, flnb, fw2, fb2, (float*)d_out, E);
}

// round 9
// speedup vs baseline: 4.2767x; 1.3065x over previous
#include <cuda_runtime.h>
#include <cuda_fp16.h>
#include <cstdint>

// ---------------------------------------------------------------------------
// E=2,000,000 edges, N_S=N_T=100,000.
//   k0: zero segment-sum accumulators
//   k1: edge MLP; 64x64 layers via warp-level mma.sync m16n8k16 fp16 3-term
//       hi/lo split. Layer1->Layer2 transition fully register-resident:
//       bias+LeakyReLU+LayerNorm in fragment layout (shfl row-reduce), D frag
//       re-packed directly to A frag (identical thread mapping). Exit dot in
//       fragment layout. SMEM used only for weights + the entry re-layout.
//   k2: coef MLP (4->32->1) scalar.
// ---------------------------------------------------------------------------

#define MAX_E  2000000
#define MAX_N  100000
#define EPSLN  1e-5f
#define SLOPE  0.01f

__device__ float g_y[MAX_E];
__device__ float g_sum_s[MAX_N];
__device__ float g_sum_t[MAX_N];

// ---------------------------------------------------------------------------
__global__ void zero_kernel(int ns, int nt) {
    int i = blockIdx.x * blockDim.x + threadIdx.x;
    if (i < ns) g_sum_s[i] = 0.0f;
    if (i < nt) g_sum_t[i] = 0.0f;
}

// ---------------------------------------------------------------------------
__device__ __forceinline__ uint32_t smem_u32(const void* p) {
    uint32_t a;
    asm("{ .reg .u64 t; cvta.to.shared.u64 t, %1; cvt.u32.u64 %0, t; }"
        : "=r"(a) : "l"(p));
    return a;
}
__device__ __forceinline__ void lds_v2_u(uint32_t addr, uint32_t& x, uint32_t& y) {
    asm volatile("ld.shared.v2.b32 {%0,%1}, [%2];" : "=r"(x), "=r"(y) : "r"(addr));
}
__device__ __forceinline__ void sts_v2_u(uint32_t addr, uint32_t x, uint32_t y) {
    asm volatile("st.shared.v2.b32 [%0], {%1,%2};" :: "r"(addr), "r"(x), "r"(y));
}
__device__ __forceinline__ void sts_b32(uint32_t addr, uint32_t v) {
    asm volatile("st.shared.b32 [%0], %1;" :: "r"(addr), "r"(v));
}
__device__ __forceinline__ void mma_f16(float d[4], uint32_t a0, uint32_t a1,
                                        uint32_t a2, uint32_t a3,
                                        uint32_t b0, uint32_t b1) {
    asm volatile(
        "mma.sync.aligned.m16n8k16.row.col.f32.f16.f16.f32 "
        "{%0,%1,%2,%3}, {%4,%5,%6,%7}, {%8,%9}, {%0,%1,%2,%3};"
        : "+f"(d[0]), "+f"(d[1]), "+f"(d[2]), "+f"(d[3])
        : "r"(a0), "r"(a1), "r"(a2), "r"(a3), "r"(b0), "r"(b1));
}

// split two f32 values (consecutive cols) into hi/lo f16x2 packs
__device__ __forceinline__ void split2(float x0, float x1, uint32_t& hi, uint32_t& lo) {
    __half2 h = __floats2half2_rn(x0, x1);
    hi = *reinterpret_cast<uint32_t*>(&h);
    float2 hf = __half22float2(h);
    __half2 l = __floats2half2_rn(x0 - hf.x, x1 - hf.y);
    lo = *reinterpret_cast<uint32_t*>(&l);
}

// ---------------------------------------------------------------------------
#define TB     128
#define TILE   128
#define PSB    136u            // f16x2 plane row stride bytes (34 words)
#define PLANE  4352u           // 32 rows * 136
#define WREG   8704u           // per-warp entry region: hi + lo plane
#define T_BYTES   (4u * WREG)  // 34816
#define WPLANE    8704u        // 64 rows * 136
#define W_OFF     T_BYTES
#define DYN_SMEM  (T_BYTES + 4u * WPLANE)   // 69632 B

__device__ __forceinline__ uint32_t pair_slot(int p) {
    int s = p >> 3, i = p & 7;
    return (uint32_t)(8 * s + ((i < 4) ? (2 * i) : (2 * (i - 4) + 1)));
}

__device__ __forceinline__ void lnorm64(float h[64], const float* __restrict__ w,
                                        const float* __restrict__ b) {
    float s = 0.f;
#pragma unroll
    for (int k = 0; k < 64; k++) s += h[k];
    float m = s * (1.0f / 64.0f);
    float v = 0.f;
#pragma unroll
    for (int k = 0; k < 64; k++) { float d = h[k] - m; v += d * d; }
    v *= (1.0f / 64.0f);
    float inv = rsqrtf(v + EPSLN);
#pragma unroll
    for (int k = 0; k < 64; k++) h[k] = (h[k] - m) * inv * w[k] + b[k];
}

__device__ __forceinline__ void store_row_f16(uint32_t region, int rloc, const float h[64]) {
    uint32_t rb = region + (uint32_t)rloc * PSB;
#pragma unroll
    for (int s = 0; s < 4; s++) {
#pragma unroll
        for (int i = 0; i < 4; i++) {
            int pa = 8 * s + i, pb = pa + 4;
            uint32_t hiA, loA, hiB, loB;
            split2(h[2 * pa], h[2 * pa + 1], hiA, loA);
            split2(h[2 * pb], h[2 * pb + 1], hiB, loB);
            uint32_t off = (uint32_t)(8 * s + 2 * i) * 4u;
            sts_v2_u(rb + off, hiA, hiB);
            sts_v2_u(rb + PLANE + off, loA, loB);
        }
    }
}

// 64x64 layer from prebuilt A fragments; acc zeroed inside.
__device__ __forceinline__ void mma_frags(float acc[2][8][4],
                                          const uint32_t Ah[2][4][4],
                                          const uint32_t Al[2][4][4],
                                          uint32_t wh, uint32_t wl, int lane) {
    int qrow = lane >> 2, qc = lane & 3;
#pragma unroll
    for (int mt = 0; mt < 2; mt++)
#pragma unroll
        for (int n = 0; n < 8; n++)
#pragma unroll
            for (int f = 0; f < 4; f++) acc[mt][n][f] = 0.f;

#pragma unroll
    for (int s = 0; s < 4; s++) {
#pragma unroll
        for (int n = 0; n < 8; n++) {
            uint32_t bh0, bh1, bl0, bl1;
            uint32_t ba = (uint32_t)(8 * n + qrow) * PSB + (uint32_t)(8 * s + 2 * qc) * 4u;
            lds_v2_u(wh + ba, bh0, bh1);
            lds_v2_u(wl + ba, bl0, bl1);
#pragma unroll
            for (int mt = 0; mt < 2; mt++) {
                mma_f16(acc[mt][n], Ah[mt][s][0], Ah[mt][s][1], Ah[mt][s][2], Ah[mt][s][3], bh0, bh1);
                mma_f16(acc[mt][n], Al[mt][s][0], Al[mt][s][1], Al[mt][s][2], Al[mt][s][3], bh0, bh1);
                mma_f16(acc[mt][n], Ah[mt][s][0], Ah[mt][s][1], Ah[mt][s][2], Ah[mt][s][3], bl0, bl1);
            }
        }
    }
}

// bias + LeakyReLU + LayerNorm entirely in D-fragment layout.
// Rows per thread: j=2*mt+half -> row 16*mt + 8*half + qrow; 16 values each,
// spread over the 4 qc lanes (shfl-xor 1,2 completes row sums).
__device__ __forceinline__ void frag_postln(float acc[2][8][4],
                                            const float* __restrict__ bias,
                                            const float* __restrict__ lw,
                                            const float* __restrict__ lb,
                                            int lane) {
    int qc = lane & 3;
    float ls[4] = {0.f, 0.f, 0.f, 0.f};
    float lq[4] = {0.f, 0.f, 0.f, 0.f};
#pragma unroll
    for (int mt = 0; mt < 2; mt++) {
#pragma unroll
        for (int n = 0; n < 8; n++) {
            int c0 = 8 * n + 2 * qc;
            float b0v = bias[c0], b1v = bias[c0 + 1];
            float t0 = acc[mt][n][0] + b0v;
            float t1 = acc[mt][n][1] + b1v;
            float t2 = acc[mt][n][2] + b0v;
            float t3 = acc[mt][n][3] + b1v;
            t0 = t0 > 0.f ? t0 : SLOPE * t0;
            t1 = t1 > 0.f ? t1 : SLOPE * t1;
            t2 = t2 > 0.f ? t2 : SLOPE * t2;
            t3 = t3 > 0.f ? t3 : SLOPE * t3;
            acc[mt][n][0] = t0; acc[mt][n][1] = t1;
            acc[mt][n][2] = t2; acc[mt][n][3] = t3;
            ls[2 * mt]     += t0 + t1;  lq[2 * mt]     += t0 * t0 + t1 * t1;
            ls[2 * mt + 1] += t2 + t3;  lq[2 * mt + 1] += t2 * t2 + t3 * t3;
        }
    }
#pragma unroll
    for (int j = 0; j < 4; j++) {
        ls[j] += __shfl_xor_sync(0xffffffffu, ls[j], 1);
        lq[j] += __shfl_xor_sync(0xffffffffu, lq[j], 1);
        ls[j] += __shfl_xor_sync(0xffffffffu, ls[j], 2);
        lq[j] += __shfl_xor_sync(0xffffffffu, lq[j], 2);
    }
    float m[4], inv[4];
#pragma unroll
    for (int j = 0; j < 4; j++) {
        m[j] = ls[j] * (1.0f / 64.0f);
        float v = lq[j] * (1.0f / 64.0f) - m[j] * m[j];
        inv[j] = rsqrtf(v + EPSLN);
    }
#pragma unroll
    for (int mt = 0; mt < 2; mt++) {
#pragma unroll
        for (int n = 0; n < 8; n++) {
            int c0 = 8 * n + 2 * qc;
            float w0v = lw[c0], w1v = lw[c0 + 1];
            float a0v = lb[c0], a1v = lb[c0 + 1];
            acc[mt][n][0] = (acc[mt][n][0] - m[2 * mt]) * inv[2 * mt] * w0v + a0v;
            acc[mt][n][1] = (acc[mt][n][1] - m[2 * mt]) * inv[2 * mt] * w1v + a1v;
            acc[mt][n][2] = (acc[mt][n][2] - m[2 * mt + 1]) * inv[2 * mt + 1] * w0v + a0v;
            acc[mt][n][3] = (acc[mt][n][3] - m[2 * mt + 1]) * inv[2 * mt + 1] * w1v + a1v;
        }
    }
}

// D fragment -> A fragment repack (identical thread mapping): k-step s takes
// n=2s (cols 16s+2qc..+1 -> a0/a1) and n=2s+1 (cols 16s+8+2qc..+1 -> a2/a3).
__device__ __forceinline__ void frags_from_acc(const float acc[2][8][4],
                                               uint32_t Ah[2][4][4],
                                               uint32_t Al[2][4][4]) {
#pragma unroll
    for (int mt = 0; mt < 2; mt++) {
#pragma unroll
        for (int s = 0; s < 4; s++) {
            split2(acc[mt][2 * s][0],     acc[mt][2 * s][1],     Ah[mt][s][0], Al[mt][s][0]);
            split2(acc[mt][2 * s][2],     acc[mt][2 * s][3],     Ah[mt][s][1], Al[mt][s][1]);
            split2(acc[mt][2 * s + 1][0], acc[mt][2 * s + 1][1], Ah[mt][s][2], Al[mt][s][2]);
            split2(acc[mt][2 * s + 1][2], acc[mt][2 * s + 1][3], Ah[mt][s][3], Al[mt][s][3]);
        }
    }
}

__global__ __launch_bounds__(TB)
void edge_kernel(const float* __restrict__ x_s, const float* __restrict__ x_t,
                 const int* __restrict__ ei, const float* __restrict__ ea,
                 const float* __restrict__ w0, const float* __restrict__ b0,
                 const float* __restrict__ w1, const float* __restrict__ b1,
                 const float* __restrict__ w2, const float* __restrict__ b2,
                 const float* __restrict__ w3, const float* __restrict__ b3,
                 const float* __restrict__ lnw, const float* __restrict__ lnb,
                 int E) {
    extern __shared__ __align__(16) char dsm[];
    uint32_t dbase = smem_u32(dsm);
    uint32_t w1h = dbase + W_OFF;
    uint32_t w1l = w1h + WPLANE;
    uint32_t w2h = w1l + WPLANE;
    uint32_t w2l = w2h + WPLANE;

    __shared__ float w0s[192], b0s[64], b1s[64], b2s[64], w3s[64];
    __shared__ float lnws[192], lnbs[192];
    __shared__ float b3s;

    int tid = threadIdx.x;
    int warp = tid >> 5, lane = tid & 31;
    int qrow = lane >> 2, qc = lane & 3;
    uint32_t region = dbase + (uint32_t)warp * WREG;

    // weights -> hi/lo f16x2 planes
    {
        const float2* w1v = (const float2*)w1;
        const float2* w2v = (const float2*)w2;
        for (int q = tid; q < 2048; q += TB) {
            int row = q >> 5, p = q & 31;
            uint32_t off = (uint32_t)row * PSB + pair_slot(p) * 4u;
            float2 a = w1v[q];
            uint32_t hi, lo;
            split2(a.x, a.y, hi, lo);
            sts_b32(w1h + off, hi);
            sts_b32(w1l + off, lo);
            float2 c = w2v[q];
            split2(c.x, c.y, hi, lo);
            sts_b32(w2h + off, hi);
            sts_b32(w2l + off, lo);
        }
    }
    for (int i = tid; i < 192; i += TB) { w0s[i] = w0[i]; lnws[i] = lnw[i]; lnbs[i] = lnb[i]; }
    if (tid < 64) { b0s[tid] = b0[tid]; b1s[tid] = b1[tid]; b2s[tid] = b2[tid]; w3s[tid] = w3[tid]; }
    if (tid == 0) b3s = b3[0];
    __syncthreads();

    // gather + layer0 (3->64), per-thread row = lane
    int e = blockIdx.x * TILE + tid;
    bool active = (e < E);
    int eidx = active ? e : (E - 1);
    int src = ei[eidx];
    int dst = ei[E + eidx];
    float xsd = x_s[src * 2 + 1];
    float xsc = x_t[dst * 2 + 1];
    float att = ea[eidx];

    {
        float h[64];
#pragma unroll
        for (int j = 0; j < 64; j++) {
            float t = w0s[j * 3] * xsd + w0s[j * 3 + 1] * xsc + w0s[j * 3 + 2] * att + b0s[j];
            h[j] = t > 0.f ? t : SLOPE * t;
        }
        lnorm64(h, lnws, lnbs);
        store_row_f16(region, lane, h);
    }
    __syncwarp();

    // load A fragments for layer 1 (hi/lo) from entry planes
    uint32_t Ah[2][4][4], Al[2][4][4];
#pragma unroll
    for (int mt = 0; mt < 2; mt++) {
#pragma unroll
        for (int s = 0; s < 4; s++) {
            uint32_t r0 = region + (uint32_t)(16 * mt + qrow) * PSB
                        + (uint32_t)(8 * s + 2 * qc) * 4u;
            lds_v2_u(r0,                    Ah[mt][s][0], Ah[mt][s][2]);
            lds_v2_u(r0 + 8u * PSB,         Ah[mt][s][1], Ah[mt][s][3]);
            lds_v2_u(r0 + PLANE,            Al[mt][s][0], Al[mt][s][2]);
            lds_v2_u(r0 + PLANE + 8u * PSB, Al[mt][s][1], Al[mt][s][3]);
        }
    }

    float acc[2][8][4];
    // ---- layer 1 ----
    mma_frags(acc, Ah, Al, w1h, w1l, lane);
    frag_postln(acc, b1s, lnws + 64, lnbs + 64, lane);
    frags_from_acc(acc, Ah, Al);

    // ---- layer 2 ----
    mma_frags(acc, Ah, Al, w2h, w2l, lane);
    frag_postln(acc, b2s, lnws + 128, lnbs + 128, lane);

    // ---- final dot (fragment layout) + butterfly reduce + scatter ----
    float p[4] = {0.f, 0.f, 0.f, 0.f};
#pragma unroll
    for (int mt = 0; mt < 2; mt++) {
#pragma unroll
        for (int n = 0; n < 8; n++) {
            int c0 = 8 * n + 2 * qc;
            float wa = w3s[c0], wb = w3s[c0 + 1];
            p[2 * mt]     += acc[mt][n][0] * wa + acc[mt][n][1] * wb;
            p[2 * mt + 1] += acc[mt][n][2] * wa + acc[mt][n][3] * wb;
        }
    }
#pragma unroll
    for (int j = 0; j < 4; j++) {
        p[j] += __shfl_xor_sync(0xffffffffu, p[j], 1);
        p[j] += __shfl_xor_sync(0xffffffffu, p[j], 2);
    }
    // lane with quad-col qc writes row j=qc: row = 16*(qc>>1) + 8*(qc&1) + qrow
    int jw = qc;
    int R = 16 * (jw >> 1) + 8 * (jw & 1) + qrow;
    float yv = p[jw >> 1 == 0 ? jw : jw];   // p indexed by j=2*mt+half
    // note: j=2*mt+half with mt=jw>>1, half=jw&1 -> p[2*(jw>>1)+(jw&1)]
    yv = p[2 * (jw >> 1) + (jw & 1)];
    yv = fmaxf(yv + b3s, 0.f);
    int ew = blockIdx.x * TILE + warp * 32 + R;
    int src_w = __shfl_sync(0xffffffffu, src, R);
    int dst_w = __shfl_sync(0xffffffffu, dst, R);
    if (ew < E) {
        g_y[ew] = yv;
        atomicAdd(&g_sum_s[src_w], yv);
        atomicAdd(&g_sum_t[dst_w], yv);
    }
}

// ---------------------------------------------------------------------------
__global__ __launch_bounds__(256)
void coef_kernel(const float* __restrict__ x_s, const float* __restrict__ x_t,
                 const int* __restrict__ ei,
                 const float* __restrict__ fw1, const float* __restrict__ fb1,
                 const float* __restrict__ flnw, const float* __restrict__ flnb,
                 const float* __restrict__ fw2, const float* __restrict__ fb2,
                 float* __restrict__ out, int E) {
    __shared__ float fw1s[128], fb1s[32], flnws[32], flnbs[32], fw2s[32];
    __shared__ float fb2s;
    int tid = threadIdx.x;
    if (tid < 128) fw1s[tid] = fw1[tid];
    if (tid < 32) {
        fb1s[tid] = fb1[tid];
        flnws[tid] = flnw[tid];
        flnbs[tid] = flnb[tid];
        fw2s[tid] = fw2[tid];
    }
    if (tid == 0) fb2s = fb2[0];
    __syncthreads();

    int e = blockIdx.x * blockDim.x + tid;
    if (e >= E) return;

    int src = ei[e];
    int dst = ei[E + e];
    float xsd = x_s[src * 2 + 1];
    float xsc = x_t[dst * 2 + 1];
    float ysi = g_sum_s[src];
    float ysj = g_sum_t[dst];

    float h[32];
#pragma unroll
    for (int j = 0; j < 32; j++) {
        float t = fw1s[j * 4] * xsd + fw1s[j * 4 + 1] * ysi +
                  fw1s[j * 4 + 2] * xsc + fw1s[j * 4 + 3] * ysj + fb1s[j];
        h[j] = fmaxf(t, 0.f);
    }
    float s = 0.f;
#pragma unroll
    for (int k = 0; k < 32; k++) s += h[k];
    float m = s * (1.0f / 32.0f);
    float v = 0.f;
#pragma unroll
    for (int k = 0; k < 32; k++) { float d = h[k] - m; v += d * d; }
    v *= (1.0f / 32.0f);
    float inv = rsqrtf(v + EPSLN);

    float acc = fb2s;
#pragma unroll
    for (int k = 0; k < 32; k++) {
        float hn = (h[k] - m) * inv * flnws[k] + flnbs[k];
        acc += fw2s[k] * hn;
    }
    acc = fmaxf(acc, 0.f);
    out[e] = g_y[e] * acc;
}

// ---------------------------------------------------------------------------
extern "C" void kernel_launch(void* const* d_in, const int* in_sizes, int n_in,
                              void* d_out, int out_size) {
    const float* x_s  = (const float*)d_in[0];
    const float* x_t  = (const float*)d_in[1];
    const int*   ei   = (const int*)d_in[2];
    const float* ea   = (const float*)d_in[3];
    const float* w0   = (const float*)d_in[4];
    const float* b0   = (const float*)d_in[5];
    const float* w1   = (const float*)d_in[6];
    const float* b1   = (const float*)d_in[7];
    const float* w2   = (const float*)d_in[8];
    const float* b2   = (const float*)d_in[9];
    const float* w3   = (const float*)d_in[10];
    const float* b3   = (const float*)d_in[11];
    const float* lnw  = (const float*)d_in[12];
    const float* lnb  = (const float*)d_in[13];
    const float* fw1  = (const float*)d_in[14];
    const float* fb1  = (const float*)d_in[15];
    const float* flnw = (const float*)d_in[16];
    const float* flnb = (const float*)d_in[17];
    const float* fw2  = (const float*)d_in[18];
    const float* fb2  = (const float*)d_in[19];

    int E  = in_sizes[3];
    int NS = in_sizes[0] / 2;
    int NT = in_sizes[1] / 2;

    int nmax = NS > NT ? NS : NT;
    zero_kernel<<<(nmax + 255) / 256, 256>>>(NS, NT);

    cudaFuncSetAttribute(edge_kernel, cudaFuncAttributeMaxDynamicSharedMemorySize, DYN_SMEM);

    edge_kernel<<<(E + TILE - 1) / TILE, TB, DYN_SMEM>>>(
        x_s, x_t, ei, ea, w0, b0, w1, b1, w2, b2, w3, b3, lnw, lnb, E);

    coef_kernel<<<(E + 255) / 256, 256>>>(
        x_s, x_t, ei, fw1, fb1, flnw, flnb, fw2, fb2, (float*)d_out, E);
}

// round 10
// speedup vs baseline: 5.1467x; 1.2034x over previous
#include <cuda_runtime.h>
#include <cuda_fp16.h>
#include <cstdint>

// ---------------------------------------------------------------------------
// E=2,000,000 edges, N_S=N_T=100,000.
//   k0: zero segment-sum accumulators
//   k1: edge MLP fully register-resident: layer0 computed directly in MMA
//       fragment layout (inputs shuffled to fragment rows), 64x64 layers via
//       m16n8k16 fp16 3-term hi/lo split, LN in fragment layout, exit dot via
//       butterfly reduce. SMEM holds only weight planes. Side-writes
//       g_xy[e]=(xsd,xsc) for the coef kernel.
//   k2: coef MLP (4->32->1); x-inputs streamed from g_xy.
// ---------------------------------------------------------------------------

#define MAX_E  2000000
#define MAX_N  100000
#define EPSLN  1e-5f
#define SLOPE  0.01f

__device__ float  g_y[MAX_E];
__device__ float2 g_xy[MAX_E];
__device__ float  g_sum_s[MAX_N];
__device__ float  g_sum_t[MAX_N];

// ---------------------------------------------------------------------------
__global__ void zero_kernel(int ns, int nt) {
    int i = blockIdx.x * blockDim.x + threadIdx.x;
    if (i < ns) g_sum_s[i] = 0.0f;
    if (i < nt) g_sum_t[i] = 0.0f;
}

// ---------------------------------------------------------------------------
__device__ __forceinline__ uint32_t smem_u32(const void* p) {
    uint32_t a;
    asm("{ .reg .u64 t; cvta.to.shared.u64 t, %1; cvt.u32.u64 %0, t; }"
        : "=r"(a) : "l"(p));
    return a;
}
__device__ __forceinline__ void lds_v2_u(uint32_t addr, uint32_t& x, uint32_t& y) {
    asm volatile("ld.shared.v2.b32 {%0,%1}, [%2];" : "=r"(x), "=r"(y) : "r"(addr));
}
__device__ __forceinline__ void sts_b32(uint32_t addr, uint32_t v) {
    asm volatile("st.shared.b32 [%0], %1;" :: "r"(addr), "r"(v));
}
__device__ __forceinline__ void mma_f16(float d[4], uint32_t a0, uint32_t a1,
                                        uint32_t a2, uint32_t a3,
                                        uint32_t b0, uint32_t b1) {
    asm volatile(
        "mma.sync.aligned.m16n8k16.row.col.f32.f16.f16.f32 "
        "{%0,%1,%2,%3}, {%4,%5,%6,%7}, {%8,%9}, {%0,%1,%2,%3};"
        : "+f"(d[0]), "+f"(d[1]), "+f"(d[2]), "+f"(d[3])
        : "r"(a0), "r"(a1), "r"(a2), "r"(a3), "r"(b0), "r"(b1));
}

__device__ __forceinline__ void split2(float x0, float x1, uint32_t& hi, uint32_t& lo) {
    __half2 h = __floats2half2_rn(x0, x1);
    hi = *reinterpret_cast<uint32_t*>(&h);
    float2 hf = __half22float2(h);
    __half2 l = __floats2half2_rn(x0 - hf.x, x1 - hf.y);
    lo = *reinterpret_cast<uint32_t*>(&l);
}

// ---------------------------------------------------------------------------
#define TB     128
#define TILE   128
#define PSB    136u            // f16x2 plane row stride bytes (34 words)
#define WPLANE 8704u           // 64 rows * 136
#define DYN_SMEM (4u * WPLANE) // 34816 B (w1h, w1l, w2h, w2l)

__device__ __forceinline__ uint32_t pair_slot(int p) {
    int s = p >> 3, i = p & 7;
    return (uint32_t)(8 * s + ((i < 4) ? (2 * i) : (2 * (i - 4) + 1)));
}

// 64x64 layer from prebuilt A fragments; acc zeroed inside.
__device__ __forceinline__ void mma_frags(float acc[2][8][4],
                                          const uint32_t Ah[2][4][4],
                                          const uint32_t Al[2][4][4],
                                          uint32_t wh, uint32_t wl, int lane) {
    int qrow = lane >> 2, qc = lane & 3;
#pragma unroll
    for (int mt = 0; mt < 2; mt++)
#pragma unroll
        for (int n = 0; n < 8; n++)
#pragma unroll
            for (int f = 0; f < 4; f++) acc[mt][n][f] = 0.f;

#pragma unroll
    for (int s = 0; s < 4; s++) {
#pragma unroll
        for (int n = 0; n < 8; n++) {
            uint32_t bh0, bh1, bl0, bl1;
            uint32_t ba = (uint32_t)(8 * n + qrow) * PSB + (uint32_t)(8 * s + 2 * qc) * 4u;
            lds_v2_u(wh + ba, bh0, bh1);
            lds_v2_u(wl + ba, bl0, bl1);
#pragma unroll
            for (int mt = 0; mt < 2; mt++) {
                mma_f16(acc[mt][n], Ah[mt][s][0], Ah[mt][s][1], Ah[mt][s][2], Ah[mt][s][3], bh0, bh1);
                mma_f16(acc[mt][n], Al[mt][s][0], Al[mt][s][1], Al[mt][s][2], Al[mt][s][3], bh0, bh1);
                mma_f16(acc[mt][n], Ah[mt][s][0], Ah[mt][s][1], Ah[mt][s][2], Ah[mt][s][3], bl0, bl1);
            }
        }
    }
}

// LayerNorm only, in D-fragment layout (stats via 2 shfl-xor rounds over qc).
__device__ __forceinline__ void frag_ln(float acc[2][8][4],
                                        const float* __restrict__ lw,
                                        const float* __restrict__ lb,
                                        int lane) {
    int qc = lane & 3;
    float ls[4] = {0.f, 0.f, 0.f, 0.f};
    float lq[4] = {0.f, 0.f, 0.f, 0.f};
#pragma unroll
    for (int mt = 0; mt < 2; mt++) {
#pragma unroll
        for (int n = 0; n < 8; n++) {
            float t0 = acc[mt][n][0], t1 = acc[mt][n][1];
            float t2 = acc[mt][n][2], t3 = acc[mt][n][3];
            ls[2 * mt]     += t0 + t1;  lq[2 * mt]     += t0 * t0 + t1 * t1;
            ls[2 * mt + 1] += t2 + t3;  lq[2 * mt + 1] += t2 * t2 + t3 * t3;
        }
    }
#pragma unroll
    for (int j = 0; j < 4; j++) {
        ls[j] += __shfl_xor_sync(0xffffffffu, ls[j], 1);
        lq[j] += __shfl_xor_sync(0xffffffffu, lq[j], 1);
        ls[j] += __shfl_xor_sync(0xffffffffu, ls[j], 2);
        lq[j] += __shfl_xor_sync(0xffffffffu, lq[j], 2);
    }
    float m[4], inv[4];
#pragma unroll
    for (int j = 0; j < 4; j++) {
        m[j] = ls[j] * (1.0f / 64.0f);
        float v = lq[j] * (1.0f / 64.0f) - m[j] * m[j];
        inv[j] = rsqrtf(v + EPSLN);
    }
#pragma unroll
    for (int mt = 0; mt < 2; mt++) {
#pragma unroll
        for (int n = 0; n < 8; n++) {
            int c0 = 8 * n + 2 * qc;
            float w0v = lw[c0], w1v = lw[c0 + 1];
            float a0v = lb[c0], a1v = lb[c0 + 1];
            acc[mt][n][0] = (acc[mt][n][0] - m[2 * mt]) * inv[2 * mt] * w0v + a0v;
            acc[mt][n][1] = (acc[mt][n][1] - m[2 * mt]) * inv[2 * mt] * w1v + a1v;
            acc[mt][n][2] = (acc[mt][n][2] - m[2 * mt + 1]) * inv[2 * mt + 1] * w0v + a0v;
            acc[mt][n][3] = (acc[mt][n][3] - m[2 * mt + 1]) * inv[2 * mt + 1] * w1v + a1v;
        }
    }
}

// bias + LeakyReLU then LN, in fragment layout.
__device__ __forceinline__ void frag_postln(float acc[2][8][4],
                                            const float* __restrict__ bias,
                                            const float* __restrict__ lw,
                                            const float* __restrict__ lb,
                                            int lane) {
    int qc = lane & 3;
#pragma unroll
    for (int mt = 0; mt < 2; mt++) {
#pragma unroll
        for (int n = 0; n < 8; n++) {
            int c0 = 8 * n + 2 * qc;
            float b0v = bias[c0], b1v = bias[c0 + 1];
            float t0 = acc[mt][n][0] + b0v;
            float t1 = acc[mt][n][1] + b1v;
            float t2 = acc[mt][n][2] + b0v;
            float t3 = acc[mt][n][3] + b1v;
            acc[mt][n][0] = t0 > 0.f ? t0 : SLOPE * t0;
            acc[mt][n][1] = t1 > 0.f ? t1 : SLOPE * t1;
            acc[mt][n][2] = t2 > 0.f ? t2 : SLOPE * t2;
            acc[mt][n][3] = t3 > 0.f ? t3 : SLOPE * t3;
        }
    }
    frag_ln(acc, lw, lb, lane);
}

// D fragment -> A fragment repack (identical thread mapping).
__device__ __forceinline__ void frags_from_acc(const float acc[2][8][4],
                                               uint32_t Ah[2][4][4],
                                               uint32_t Al[2][4][4]) {
#pragma unroll
    for (int mt = 0; mt < 2; mt++) {
#pragma unroll
        for (int s = 0; s < 4; s++) {
            split2(acc[mt][2 * s][0],     acc[mt][2 * s][1],     Ah[mt][s][0], Al[mt][s][0]);
            split2(acc[mt][2 * s][2],     acc[mt][2 * s][3],     Ah[mt][s][1], Al[mt][s][1]);
            split2(acc[mt][2 * s + 1][0], acc[mt][2 * s + 1][1], Ah[mt][s][2], Al[mt][s][2]);
            split2(acc[mt][2 * s + 1][2], acc[mt][2 * s + 1][3], Ah[mt][s][3], Al[mt][s][3]);
        }
    }
}

__global__ __launch_bounds__(TB)
void edge_kernel(const float* __restrict__ x_s, const float* __restrict__ x_t,
                 const int* __restrict__ ei, const float* __restrict__ ea,
                 const float* __restrict__ w0, const float* __restrict__ b0,
                 const float* __restrict__ w1, const float* __restrict__ b1,
                 const float* __restrict__ w2, const float* __restrict__ b2,
                 const float* __restrict__ w3, const float* __restrict__ b3,
                 const float* __restrict__ lnw, const float* __restrict__ lnb,
                 int E) {
    extern __shared__ __align__(16) char dsm[];
    uint32_t dbase = smem_u32(dsm);
    uint32_t w1h = dbase;
    uint32_t w1l = w1h + WPLANE;
    uint32_t w2h = w1l + WPLANE;
    uint32_t w2l = w2h + WPLANE;

    __shared__ float w0s[192], b0s[64], b1s[64], b2s[64], w3s[64];
    __shared__ float lnws[192], lnbs[192];
    __shared__ float b3s;

    int tid = threadIdx.x;
    int warp = tid >> 5, lane = tid & 31;
    int qrow = lane >> 2, qc = lane & 3;

    // weights -> hi/lo f16x2 planes
    {
        const float2* w1v = (const float2*)w1;
        const float2* w2v = (const float2*)w2;
        for (int q = tid; q < 2048; q += TB) {
            int row = q >> 5, p = q & 31;
            uint32_t off = (uint32_t)row * PSB + pair_slot(p) * 4u;
            float2 a = w1v[q];
            uint32_t hi, lo;
            split2(a.x, a.y, hi, lo);
            sts_b32(w1h + off, hi);
            sts_b32(w1l + off, lo);
            float2 c = w2v[q];
            split2(c.x, c.y, hi, lo);
            sts_b32(w2h + off, hi);
            sts_b32(w2l + off, lo);
        }
    }
    for (int i = tid; i < 192; i += TB) { w0s[i] = w0[i]; lnws[i] = lnw[i]; lnbs[i] = lnb[i]; }
    if (tid < 64) { b0s[tid] = b0[tid]; b1s[tid] = b1[tid]; b2s[tid] = b2[tid]; w3s[tid] = w3[tid]; }
    if (tid == 0) b3s = b3[0];
    __syncthreads();

    // gather (per lane: edge = warp tile base + lane)
    int e = blockIdx.x * TILE + tid;
    bool active = (e < E);
    int eidx = active ? e : (E - 1);
    int src = ei[eidx];
    int dst = ei[E + eidx];
    float xsd = x_s[src * 2 + 1];
    float xsc = x_t[dst * 2 + 1];
    float att = ea[eidx];

    if (active) g_xy[e] = make_float2(xsd, xsc);

    // shuffle inputs to fragment rows: j=2*mt+half -> row 16*mt+8*half+qrow
    float xs4[4], xc4[4], at4[4];
#pragma unroll
    for (int j = 0; j < 4; j++) {
        int R = 16 * (j >> 1) + 8 * (j & 1) + qrow;
        xs4[j] = __shfl_sync(0xffffffffu, xsd, R);
        xc4[j] = __shfl_sync(0xffffffffu, xsc, R);
        at4[j] = __shfl_sync(0xffffffffu, att, R);
    }

    // layer0 (3->64) directly in fragment layout + LeakyReLU
    float acc[2][8][4];
#pragma unroll
    for (int mt = 0; mt < 2; mt++) {
#pragma unroll
        for (int n = 0; n < 8; n++) {
            int c0 = 8 * n + 2 * qc;
#pragma unroll
            for (int half = 0; half < 2; half++) {
                int j = 2 * mt + half;
#pragma unroll
                for (int cc = 0; cc < 2; cc++) {
                    int c = c0 + cc;
                    float t = w0s[c * 3] * xs4[j] + w0s[c * 3 + 1] * xc4[j]
                            + w0s[c * 3 + 2] * at4[j] + b0s[c];
                    acc[mt][n][2 * half + cc] = t > 0.f ? t : SLOPE * t;
                }
            }
        }
    }
    frag_ln(acc, lnws, lnbs, lane);

    uint32_t Ah[2][4][4], Al[2][4][4];
    frags_from_acc(acc, Ah, Al);

    // ---- layer 1 ----
    mma_frags(acc, Ah, Al, w1h, w1l, lane);
    frag_postln(acc, b1s, lnws + 64, lnbs + 64, lane);
    frags_from_acc(acc, Ah, Al);

    // ---- layer 2 ----
    mma_frags(acc, Ah, Al, w2h, w2l, lane);
    frag_postln(acc, b2s, lnws + 128, lnbs + 128, lane);

    // ---- final dot (fragment layout) + butterfly reduce + scatter ----
    float p[4] = {0.f, 0.f, 0.f, 0.f};
#pragma unroll
    for (int mt = 0; mt < 2; mt++) {
#pragma unroll
        for (int n = 0; n < 8; n++) {
            int c0 = 8 * n + 2 * qc;
            float wa = w3s[c0], wb = w3s[c0 + 1];
            p[2 * mt]     += acc[mt][n][0] * wa + acc[mt][n][1] * wb;
            p[2 * mt + 1] += acc[mt][n][2] * wa + acc[mt][n][3] * wb;
        }
    }
#pragma unroll
    for (int j = 0; j < 4; j++) {
        p[j] += __shfl_xor_sync(0xffffffffu, p[j], 1);
        p[j] += __shfl_xor_sync(0xffffffffu, p[j], 2);
    }
    int jw = qc;                                   // this lane outputs row-group jw
    int R = 16 * (jw >> 1) + 8 * (jw & 1) + qrow;  // row within warp tile
    float yv = fmaxf(p[2 * (jw >> 1) + (jw & 1)] + b3s, 0.f);
    int ew = blockIdx.x * TILE + warp * 32 + R;
    int src_w = __shfl_sync(0xffffffffu, src, R);
    int dst_w = __shfl_sync(0xffffffffu, dst, R);
    if (ew < E) {
        g_y[ew] = yv;
        atomicAdd(&g_sum_s[src_w], yv);
        atomicAdd(&g_sum_t[dst_w], yv);
    }
}

// ---------------------------------------------------------------------------
__global__ __launch_bounds__(256)
void coef_kernel(const int* __restrict__ ei,
                 const float* __restrict__ fw1, const float* __restrict__ fb1,
                 const float* __restrict__ flnw, const float* __restrict__ flnb,
                 const float* __restrict__ fw2, const float* __restrict__ fb2,
                 float* __restrict__ out, int E) {
    __shared__ float fw1s[128], fb1s[32], flnws[32], flnbs[32], fw2s[32];
    __shared__ float fb2s;
    int tid = threadIdx.x;
    if (tid < 128) fw1s[tid] = fw1[tid];
    if (tid < 32) {
        fb1s[tid] = fb1[tid];
        flnws[tid] = flnw[tid];
        flnbs[tid] = flnb[tid];
        fw2s[tid] = fw2[tid];
    }
    if (tid == 0) fb2s = fb2[0];
    __syncthreads();

    int e = blockIdx.x * blockDim.x + tid;
    if (e >= E) return;

    int src = ei[e];
    int dst = ei[E + e];
    float2 xy = g_xy[e];
    float xsd = xy.x;
    float xsc = xy.y;
    float ysi = g_sum_s[src];
    float ysj = g_sum_t[dst];

    float h[32];
#pragma unroll
    for (int j = 0; j < 32; j++) {
        float t = fw1s[j * 4] * xsd + fw1s[j * 4 + 1] * ysi +
                  fw1s[j * 4 + 2] * xsc + fw1s[j * 4 + 3] * ysj + fb1s[j];
        h[j] = fmaxf(t, 0.f);
    }
    float s = 0.f;
#pragma unroll
    for (int k = 0; k < 32; k++) s += h[k];
    float m = s * (1.0f / 32.0f);
    float v = 0.f;
#pragma unroll
    for (int k = 0; k < 32; k++) { float d = h[k] - m; v += d * d; }
    v *= (1.0f / 32.0f);
    float inv = rsqrtf(v + EPSLN);

    float acc = fb2s;
#pragma unroll
    for (int k = 0; k < 32; k++) {
        float hn = (h[k] - m) * inv * flnws[k] + flnbs[k];
        acc += fw2s[k] * hn;
    }
    acc = fmaxf(acc, 0.f);
    out[e] = g_y[e] * acc;
}

// ---------------------------------------------------------------------------
extern "C" void kernel_launch(void* const* d_in, const int* in_sizes, int n_in,
                              void* d_out, int out_size) {
    const float* x_s  = (const float*)d_in[0];
    const float* x_t  = (const float*)d_in[1];
    const int*   ei   = (const int*)d_in[2];
    const float* ea   = (const float*)d_in[3];
    const float* w0   = (const float*)d_in[4];
    const float* b0   = (const float*)d_in[5];
    const float* w1   = (const float*)d_in[6];
    const float* b1   = (const float*)d_in[7];
    const float* w2   = (const float*)d_in[8];
    const float* b2   = (const float*)d_in[9];
    const float* w3   = (const float*)d_in[10];
    const float* b3   = (const float*)d_in[11];
    const float* lnw  = (const float*)d_in[12];
    const float* lnb  = (const float*)d_in[13];
    const float* fw1  = (const float*)d_in[14];
    const float* fb1  = (const float*)d_in[15];
    const float* flnw = (const float*)d_in[16];
    const float* flnb = (const float*)d_in[17];
    const float* fw2  = (const float*)d_in[18];
    const float* fb2  = (const float*)d_in[19];

    int E  = in_sizes[3];
    int NS = in_sizes[0] / 2;
    int NT = in_sizes[1] / 2;

    int nmax = NS > NT ? NS : NT;
    zero_kernel<<<(nmax + 255) / 256, 256>>>(NS, NT);

    cudaFuncSetAttribute(edge_kernel, cudaFuncAttributeMaxDynamicSharedMemorySize, DYN_SMEM);

    edge_kernel<<<(E + TILE - 1) / TILE, TB, DYN_SMEM>>>(
        x_s, x_t, ei, ea, w0, b0, w1, b1, w2, b2, w3, b3, lnw, lnb, E);

    coef_kernel<<<(E + 255) / 256, 256>>>(
        ei, fw1, fb1, flnw, flnb, fw2, fb2, (float*)d_out, E);
}

// round 11
// speedup vs baseline: 5.5013x; 1.0689x over previous
#include <cuda_runtime.h>
#include <cuda_fp16.h>
#include <cstdint>

// ---------------------------------------------------------------------------
// E=2,000,000 edges, N_S=N_T=100,000.
//   k0: zero segment-sum accumulators
//   k1: edge MLP, persistent warps: weights converted to hi/lo f16x2 planes
//       once per CTA; each warp grid-strides over 32-edge chunks, fully
//       register-resident MLP (m16n8k16 fp16 3-term hi/lo, LN in fragment
//       layout, exit dot via butterfly reduce). Side-writes g_xy.
//   k2: coef MLP (4->32->1); x-inputs streamed from g_xy.
// ---------------------------------------------------------------------------

#define MAX_E  2000000
#define MAX_N  100000
#define EPSLN  1e-5f
#define SLOPE  0.01f

__device__ float  g_y[MAX_E];
__device__ float2 g_xy[MAX_E];
__device__ float  g_sum_s[MAX_N];
__device__ float  g_sum_t[MAX_N];

// ---------------------------------------------------------------------------
__global__ void zero_kernel(int ns, int nt) {
    int i = blockIdx.x * blockDim.x + threadIdx.x;
    if (i < ns) g_sum_s[i] = 0.0f;
    if (i < nt) g_sum_t[i] = 0.0f;
}

// ---------------------------------------------------------------------------
__device__ __forceinline__ uint32_t smem_u32(const void* p) {
    uint32_t a;
    asm("{ .reg .u64 t; cvta.to.shared.u64 t, %1; cvt.u32.u64 %0, t; }"
        : "=r"(a) : "l"(p));
    return a;
}
__device__ __forceinline__ void lds_v2_u(uint32_t addr, uint32_t& x, uint32_t& y) {
    asm volatile("ld.shared.v2.b32 {%0,%1}, [%2];" : "=r"(x), "=r"(y) : "r"(addr));
}
__device__ __forceinline__ void sts_b32(uint32_t addr, uint32_t v) {
    asm volatile("st.shared.b32 [%0], %1;" :: "r"(addr), "r"(v));
}
__device__ __forceinline__ void mma_f16(float d[4], uint32_t a0, uint32_t a1,
                                        uint32_t a2, uint32_t a3,
                                        uint32_t b0, uint32_t b1) {
    asm volatile(
        "mma.sync.aligned.m16n8k16.row.col.f32.f16.f16.f32 "
        "{%0,%1,%2,%3}, {%4,%5,%6,%7}, {%8,%9}, {%0,%1,%2,%3};"
        : "+f"(d[0]), "+f"(d[1]), "+f"(d[2]), "+f"(d[3])
        : "r"(a0), "r"(a1), "r"(a2), "r"(a3), "r"(b0), "r"(b1));
}

__device__ __forceinline__ void split2(float x0, float x1, uint32_t& hi, uint32_t& lo) {
    __half2 h = __floats2half2_rn(x0, x1);
    hi = *reinterpret_cast<uint32_t*>(&h);
    float2 hf = __half22float2(h);
    __half2 l = __floats2half2_rn(x0 - hf.x, x1 - hf.y);
    lo = *reinterpret_cast<uint32_t*>(&l);
}

// ---------------------------------------------------------------------------
#define TB     128
#define PSB    136u            // f16x2 plane row stride bytes (34 words)
#define WPLANE 8704u           // 64 rows * 136
#define DYN_SMEM (4u * WPLANE) // 34816 B (w1h, w1l, w2h, w2l)
#define NCTA   444             // 148 SMs * 3

__device__ __forceinline__ uint32_t pair_slot(int p) {
    int s = p >> 3, i = p & 7;
    return (uint32_t)(8 * s + ((i < 4) ? (2 * i) : (2 * (i - 4) + 1)));
}

// 64x64 layer from prebuilt A fragments; acc zeroed inside.
__device__ __forceinline__ void mma_frags(float acc[2][8][4],
                                          const uint32_t Ah[2][4][4],
                                          const uint32_t Al[2][4][4],
                                          uint32_t wh, uint32_t wl, int lane) {
    int qrow = lane >> 2, qc = lane & 3;
#pragma unroll
    for (int mt = 0; mt < 2; mt++)
#pragma unroll
        for (int n = 0; n < 8; n++)
#pragma unroll
            for (int f = 0; f < 4; f++) acc[mt][n][f] = 0.f;

#pragma unroll
    for (int s = 0; s < 4; s++) {
#pragma unroll
        for (int n = 0; n < 8; n++) {
            uint32_t bh0, bh1, bl0, bl1;
            uint32_t ba = (uint32_t)(8 * n + qrow) * PSB + (uint32_t)(8 * s + 2 * qc) * 4u;
            lds_v2_u(wh + ba, bh0, bh1);
            lds_v2_u(wl + ba, bl0, bl1);
#pragma unroll
            for (int mt = 0; mt < 2; mt++) {
                mma_f16(acc[mt][n], Ah[mt][s][0], Ah[mt][s][1], Ah[mt][s][2], Ah[mt][s][3], bh0, bh1);
                mma_f16(acc[mt][n], Al[mt][s][0], Al[mt][s][1], Al[mt][s][2], Al[mt][s][3], bh0, bh1);
                mma_f16(acc[mt][n], Ah[mt][s][0], Ah[mt][s][1], Ah[mt][s][2], Ah[mt][s][3], bl0, bl1);
            }
        }
    }
}

// LayerNorm in D-fragment layout (stats via 2 shfl-xor rounds over qc).
__device__ __forceinline__ void frag_ln(float acc[2][8][4],
                                        const float* __restrict__ lw,
                                        const float* __restrict__ lb,
                                        int lane) {
    int qc = lane & 3;
    float ls[4] = {0.f, 0.f, 0.f, 0.f};
    float lq[4] = {0.f, 0.f, 0.f, 0.f};
#pragma unroll
    for (int mt = 0; mt < 2; mt++) {
#pragma unroll
        for (int n = 0; n < 8; n++) {
            float t0 = acc[mt][n][0], t1 = acc[mt][n][1];
            float t2 = acc[mt][n][2], t3 = acc[mt][n][3];
            ls[2 * mt]     += t0 + t1;  lq[2 * mt]     += t0 * t0 + t1 * t1;
            ls[2 * mt + 1] += t2 + t3;  lq[2 * mt + 1] += t2 * t2 + t3 * t3;
        }
    }
#pragma unroll
    for (int j = 0; j < 4; j++) {
        ls[j] += __shfl_xor_sync(0xffffffffu, ls[j], 1);
        lq[j] += __shfl_xor_sync(0xffffffffu, lq[j], 1);
        ls[j] += __shfl_xor_sync(0xffffffffu, ls[j], 2);
        lq[j] += __shfl_xor_sync(0xffffffffu, lq[j], 2);
    }
    float m[4], inv[4];
#pragma unroll
    for (int j = 0; j < 4; j++) {
        m[j] = ls[j] * (1.0f / 64.0f);
        float v = lq[j] * (1.0f / 64.0f) - m[j] * m[j];
        inv[j] = rsqrtf(v + EPSLN);
    }
#pragma unroll
    for (int mt = 0; mt < 2; mt++) {
#pragma unroll
        for (int n = 0; n < 8; n++) {
            int c0 = 8 * n + 2 * qc;
            float w0v = lw[c0], w1v = lw[c0 + 1];
            float a0v = lb[c0], a1v = lb[c0 + 1];
            acc[mt][n][0] = (acc[mt][n][0] - m[2 * mt]) * inv[2 * mt] * w0v + a0v;
            acc[mt][n][1] = (acc[mt][n][1] - m[2 * mt]) * inv[2 * mt] * w1v + a1v;
            acc[mt][n][2] = (acc[mt][n][2] - m[2 * mt + 1]) * inv[2 * mt + 1] * w0v + a0v;
            acc[mt][n][3] = (acc[mt][n][3] - m[2 * mt + 1]) * inv[2 * mt + 1] * w1v + a1v;
        }
    }
}

// bias + LeakyReLU then LN, in fragment layout.
__device__ __forceinline__ void frag_postln(float acc[2][8][4],
                                            const float* __restrict__ bias,
                                            const float* __restrict__ lw,
                                            const float* __restrict__ lb,
                                            int lane) {
    int qc = lane & 3;
#pragma unroll
    for (int mt = 0; mt < 2; mt++) {
#pragma unroll
        for (int n = 0; n < 8; n++) {
            int c0 = 8 * n + 2 * qc;
            float b0v = bias[c0], b1v = bias[c0 + 1];
            float t0 = acc[mt][n][0] + b0v;
            float t1 = acc[mt][n][1] + b1v;
            float t2 = acc[mt][n][2] + b0v;
            float t3 = acc[mt][n][3] + b1v;
            acc[mt][n][0] = t0 > 0.f ? t0 : SLOPE * t0;
            acc[mt][n][1] = t1 > 0.f ? t1 : SLOPE * t1;
            acc[mt][n][2] = t2 > 0.f ? t2 : SLOPE * t2;
            acc[mt][n][3] = t3 > 0.f ? t3 : SLOPE * t3;
        }
    }
    frag_ln(acc, lw, lb, lane);
}

// D fragment -> A fragment repack (identical thread mapping).
__device__ __forceinline__ void frags_from_acc(const float acc[2][8][4],
                                               uint32_t Ah[2][4][4],
                                               uint32_t Al[2][4][4]) {
#pragma unroll
    for (int mt = 0; mt < 2; mt++) {
#pragma unroll
        for (int s = 0; s < 4; s++) {
            split2(acc[mt][2 * s][0],     acc[mt][2 * s][1],     Ah[mt][s][0], Al[mt][s][0]);
            split2(acc[mt][2 * s][2],     acc[mt][2 * s][3],     Ah[mt][s][1], Al[mt][s][1]);
            split2(acc[mt][2 * s + 1][0], acc[mt][2 * s + 1][1], Ah[mt][s][2], Al[mt][s][2]);
            split2(acc[mt][2 * s + 1][2], acc[mt][2 * s + 1][3], Ah[mt][s][3], Al[mt][s][3]);
        }
    }
}

__global__ __launch_bounds__(TB)
void edge_kernel(const float* __restrict__ x_s, const float* __restrict__ x_t,
                 const int* __restrict__ ei, const float* __restrict__ ea,
                 const float* __restrict__ w0, const float* __restrict__ b0,
                 const float* __restrict__ w1, const float* __restrict__ b1,
                 const float* __restrict__ w2, const float* __restrict__ b2,
                 const float* __restrict__ w3, const float* __restrict__ b3,
                 const float* __restrict__ lnw, const float* __restrict__ lnb,
                 int E) {
    extern __shared__ __align__(16) char dsm[];
    uint32_t dbase = smem_u32(dsm);
    uint32_t w1h = dbase;
    uint32_t w1l = w1h + WPLANE;
    uint32_t w2h = w1l + WPLANE;
    uint32_t w2l = w2h + WPLANE;

    __shared__ float w0s[192], b0s[64], b1s[64], b2s[64], w3s[64];
    __shared__ float lnws[192], lnbs[192];
    __shared__ float b3s;

    int tid = threadIdx.x;
    int warp = tid >> 5, lane = tid & 31;
    int qrow = lane >> 2, qc = lane & 3;

    // ---- one-time prologue: weights -> hi/lo f16x2 planes ----
    {
        const float2* w1v = (const float2*)w1;
        const float2* w2v = (const float2*)w2;
        for (int q = tid; q < 2048; q += TB) {
            int row = q >> 5, p = q & 31;
            uint32_t off = (uint32_t)row * PSB + pair_slot(p) * 4u;
            float2 a = w1v[q];
            uint32_t hi, lo;
            split2(a.x, a.y, hi, lo);
            sts_b32(w1h + off, hi);
            sts_b32(w1l + off, lo);
            float2 c = w2v[q];
            split2(c.x, c.y, hi, lo);
            sts_b32(w2h + off, hi);
            sts_b32(w2l + off, lo);
        }
    }
    for (int i = tid; i < 192; i += TB) { w0s[i] = w0[i]; lnws[i] = lnw[i]; lnbs[i] = lnb[i]; }
    if (tid < 64) { b0s[tid] = b0[tid]; b1s[tid] = b1[tid]; b2s[tid] = b2[tid]; w3s[tid] = w3[tid]; }
    if (tid == 0) b3s = b3[0];
    __syncthreads();

    // ---- persistent per-warp loop over 32-edge chunks ----
    int nchunks = (E + 31) >> 5;
    int gw = blockIdx.x * (TB / 32) + warp;
    int wstride = gridDim.x * (TB / 32);

    for (int ch = gw; ch < nchunks; ch += wstride) {
        int e = ch * 32 + lane;
        bool active = (e < E);
        int eidx = active ? e : (E - 1);
        int src = ei[eidx];
        int dst = ei[E + eidx];
        float xsd = x_s[src * 2 + 1];
        float xsc = x_t[dst * 2 + 1];
        float att = ea[eidx];

        if (active) g_xy[e] = make_float2(xsd, xsc);

        // shuffle inputs to fragment rows: j=2*mt+half -> row 16*mt+8*half+qrow
        float xs4[4], xc4[4], at4[4];
#pragma unroll
        for (int j = 0; j < 4; j++) {
            int R = 16 * (j >> 1) + 8 * (j & 1) + qrow;
            xs4[j] = __shfl_sync(0xffffffffu, xsd, R);
            xc4[j] = __shfl_sync(0xffffffffu, xsc, R);
            at4[j] = __shfl_sync(0xffffffffu, att, R);
        }

        // layer0 (3->64) directly in fragment layout + LeakyReLU
        float acc[2][8][4];
#pragma unroll
        for (int mt = 0; mt < 2; mt++) {
#pragma unroll
            for (int n = 0; n < 8; n++) {
                int c0 = 8 * n + 2 * qc;
#pragma unroll
                for (int half = 0; half < 2; half++) {
                    int j = 2 * mt + half;
#pragma unroll
                    for (int cc = 0; cc < 2; cc++) {
                        int c = c0 + cc;
                        float t = w0s[c * 3] * xs4[j] + w0s[c * 3 + 1] * xc4[j]
                                + w0s[c * 3 + 2] * at4[j] + b0s[c];
                        acc[mt][n][2 * half + cc] = t > 0.f ? t : SLOPE * t;
                    }
                }
            }
        }
        frag_ln(acc, lnws, lnbs, lane);

        uint32_t Ah[2][4][4], Al[2][4][4];
        frags_from_acc(acc, Ah, Al);

        // ---- layer 1 ----
        mma_frags(acc, Ah, Al, w1h, w1l, lane);
        frag_postln(acc, b1s, lnws + 64, lnbs + 64, lane);
        frags_from_acc(acc, Ah, Al);

        // ---- layer 2 ----
        mma_frags(acc, Ah, Al, w2h, w2l, lane);
        frag_postln(acc, b2s, lnws + 128, lnbs + 128, lane);

        // ---- final dot + butterfly reduce + scatter ----
        float p[4] = {0.f, 0.f, 0.f, 0.f};
#pragma unroll
        for (int mt = 0; mt < 2; mt++) {
#pragma unroll
            for (int n = 0; n < 8; n++) {
                int c0 = 8 * n + 2 * qc;
                float wa = w3s[c0], wb = w3s[c0 + 1];
                p[2 * mt]     += acc[mt][n][0] * wa + acc[mt][n][1] * wb;
                p[2 * mt + 1] += acc[mt][n][2] * wa + acc[mt][n][3] * wb;
            }
        }
#pragma unroll
        for (int j = 0; j < 4; j++) {
            p[j] += __shfl_xor_sync(0xffffffffu, p[j], 1);
            p[j] += __shfl_xor_sync(0xffffffffu, p[j], 2);
        }
        int jw = qc;
        int R = 16 * (jw >> 1) + 8 * (jw & 1) + qrow;
        float yv = fmaxf(p[2 * (jw >> 1) + (jw & 1)] + b3s, 0.f);
        int ew = ch * 32 + R;
        int src_w = __shfl_sync(0xffffffffu, src, R);
        int dst_w = __shfl_sync(0xffffffffu, dst, R);
        if (ew < E) {
            g_y[ew] = yv;
            atomicAdd(&g_sum_s[src_w], yv);
            atomicAdd(&g_sum_t[dst_w], yv);
        }
    }
}

// ---------------------------------------------------------------------------
__global__ __launch_bounds__(256)
void coef_kernel(const int* __restrict__ ei,
                 const float* __restrict__ fw1, const float* __restrict__ fb1,
                 const float* __restrict__ flnw, const float* __restrict__ flnb,
                 const float* __restrict__ fw2, const float* __restrict__ fb2,
                 float* __restrict__ out, int E) {
    __shared__ float fw1s[128], fb1s[32], flnws[32], flnbs[32], fw2s[32];
    __shared__ float fb2s;
    int tid = threadIdx.x;
    if (tid < 128) fw1s[tid] = fw1[tid];
    if (tid < 32) {
        fb1s[tid] = fb1[tid];
        flnws[tid] = flnw[tid];
        flnbs[tid] = flnb[tid];
        fw2s[tid] = fw2[tid];
    }
    if (tid == 0) fb2s = fb2[0];
    __syncthreads();

    int e = blockIdx.x * blockDim.x + tid;
    if (e >= E) return;

    int src = ei[e];
    int dst = ei[E + e];
    float2 xy = g_xy[e];
    float xsd = xy.x;
    float xsc = xy.y;
    float ysi = g_sum_s[src];
    float ysj = g_sum_t[dst];

    float h[32];
#pragma unroll
    for (int j = 0; j < 32; j++) {
        float t = fw1s[j * 4] * xsd + fw1s[j * 4 + 1] * ysi +
                  fw1s[j * 4 + 2] * xsc + fw1s[j * 4 + 3] * ysj + fb1s[j];
        h[j] = fmaxf(t, 0.f);
    }
    float s = 0.f;
#pragma unroll
    for (int k = 0; k < 32; k++) s += h[k];
    float m = s * (1.0f / 32.0f);
    float v = 0.f;
#pragma unroll
    for (int k = 0; k < 32; k++) { float d = h[k] - m; v += d * d; }
    v *= (1.0f / 32.0f);
    float inv = rsqrtf(v + EPSLN);

    float acc = fb2s;
#pragma unroll
    for (int k = 0; k < 32; k++) {
        float hn = (h[k] - m) * inv * flnws[k] + flnbs[k];
        acc += fw2s[k] * hn;
    }
    acc = fmaxf(acc, 0.f);
    out[e] = g_y[e] * acc;
}

// ---------------------------------------------------------------------------
extern "C" void kernel_launch(void* const* d_in, const int* in_sizes, int n_in,
                              void* d_out, int out_size) {
    const float* x_s  = (const float*)d_in[0];
    const float* x_t  = (const float*)d_in[1];
    const int*   ei   = (const int*)d_in[2];
    const float* ea   = (const float*)d_in[3];
    const float* w0   = (const float*)d_in[4];
    const float* b0   = (const float*)d_in[5];
    const float* w1   = (const float*)d_in[6];
    const float* b1   = (const float*)d_in[7];
    const float* w2   = (const float*)d_in[8];
    const float* b2   = (const float*)d_in[9];
    const float* w3   = (const float*)d_in[10];
    const float* b3   = (const float*)d_in[11];
    const float* lnw  = (const float*)d_in[12];
    const float* lnb  = (const float*)d_in[13];
    const float* fw1  = (const float*)d_in[14];
    const float* fb1  = (const float*)d_in[15];
    const float* flnw = (const float*)d_in[16];
    const float* flnb = (const float*)d_in[17];
    const float* fw2  = (const float*)d_in[18];
    const float* fb2  = (const float*)d_in[19];

    int E  = in_sizes[3];
    int NS = in_sizes[0] / 2;
    int NT = in_sizes[1] / 2;

    int nmax = NS > NT ? NS : NT;
    zero_kernel<<<(nmax + 255) / 256, 256>>>(NS, NT);

    cudaFuncSetAttribute(edge_kernel, cudaFuncAttributeMaxDynamicSharedMemorySize, DYN_SMEM);

    int ncta = (E + TB - 1) / TB;
    if (ncta > NCTA) ncta = NCTA;
    edge_kernel<<<ncta, TB, DYN_SMEM>>>(
        x_s, x_t, ei, ea, w0, b0, w1, b1, w2, b2, w3, b3, lnw, lnb, E);

    coef_kernel<<<(E + 255) / 256, 256>>>(
        ei, fw1, fb1, flnw, flnb, fw2, fb2, (float*)d_out, E);
}